// round 9
// baseline (speedup 1.0000x reference)
#include <cuda_runtime.h>
#include <cuda_bf16.h>
#include <cstdint>

#define TOTAL 24576
#define NSEG  64

// ------------------------- device scratch (static) -------------------------
__device__ __nv_bfloat16 g_csrc[TOTAL * 256];
__device__ __nv_bfloat16 g_cdst[TOTAL * 256];
__device__ __nv_bfloat16 g_kv  [TOTAL * 256];   // head-major k|v, bf16
__device__ __nv_bfloat16 g_q   [TOTAL * 128];   // head-major q, bf16
__device__ float         g_y1a [TOTAL * 256];   // dst_h @ W1a.T + b1'
__device__ __nv_bfloat16 g_msg [TOTAL * 128];   // head-major attention out
__device__ __nv_bfloat16 g_x1  [TOTAL * 256];
__device__ __nv_bfloat16 g_Wkv [256 * 256];
__device__ __nv_bfloat16 g_Wq  [128 * 256];
__device__ __nv_bfloat16 g_W1a [256 * 256];
__device__ __nv_bfloat16 g_W1bp[256 * 128];
__device__ __nv_bfloat16 g_W2b [256 * 256];
__device__ float g_bkvp[256], g_bqp[128], g_b1p[256];
__device__ float g_s1[256], g_t1[256], g_s2[256], g_t2[256];
__device__ int g_soff[NSEG + 1], g_doff[NSEG + 1], g_scnt[NSEG], g_dcnt[NSEG];

__device__ __forceinline__ int permc(int n) { return (n & 31) * 4 + (n >> 5); }

// ------------------------------ PTX helpers --------------------------------
__device__ __forceinline__ void ldsm4(uint32_t& r0, uint32_t& r1, uint32_t& r2,
                                      uint32_t& r3, uint32_t a) {
    asm volatile("ldmatrix.sync.aligned.m8n8.x4.shared.b16 {%0,%1,%2,%3}, [%4];"
                 : "=r"(r0), "=r"(r1), "=r"(r2), "=r"(r3) : "r"(a));
}
__device__ __forceinline__ void ldsm4t(uint32_t& r0, uint32_t& r1, uint32_t& r2,
                                       uint32_t& r3, uint32_t a) {
    asm volatile("ldmatrix.sync.aligned.m8n8.x4.trans.shared.b16 {%0,%1,%2,%3}, [%4];"
                 : "=r"(r0), "=r"(r1), "=r"(r2), "=r"(r3) : "r"(a));
}
__device__ __forceinline__ void mma_bf16(float c[4], const uint32_t a[4],
                                         const uint32_t b[2]) {
    asm volatile(
        "mma.sync.aligned.m16n8k16.row.col.f32.bf16.bf16.f32 "
        "{%0,%1,%2,%3},{%4,%5,%6,%7},{%8,%9},{%0,%1,%2,%3};"
        : "+f"(c[0]), "+f"(c[1]), "+f"(c[2]), "+f"(c[3])
        : "r"(a[0]), "r"(a[1]), "r"(a[2]), "r"(a[3]), "r"(b[0]), "r"(b[1]));
}
__device__ __forceinline__ float ex2(float x) {
    float r; asm("ex2.approx.f32 %0, %1;" : "=f"(r) : "f"(x)); return r;
}
__device__ __forceinline__ uint32_t pk(float a, float b) {
    __nv_bfloat162 v = __floats2bfloat162_rn(a, b);
    return *reinterpret_cast<uint32_t*>(&v);
}
__device__ __forceinline__ void cpa16(uint32_t s, const void* g) {
    asm volatile("cp.async.cg.shared.global [%0], [%1], 16;" :: "r"(s), "l"(g));
}
__device__ __forceinline__ void cpa_commit() {
    asm volatile("cp.async.commit_group;" ::: "memory");
}
template<int N>
__device__ __forceinline__ void cpa_wait() {
    asm volatile("cp.async.wait_group %0;" :: "n"(N) : "memory");
}

// ------------------------------- K0: setup ---------------------------------
__device__ __forceinline__ int read_count(const void* p, int i, bool is64) {
    if (is64) return (int)((const long long*)p)[i];
    return ((const int*)p)[i];
}

__global__ void k_setup(const void* snv, const void* dnv,
                        const float* __restrict__ bq, const float* __restrict__ bk,
                        const float* __restrict__ bv, const float* __restrict__ bm,
                        const float* __restrict__ b1,
                        const float* __restrict__ g1, const float* __restrict__ be1,
                        const float* __restrict__ rm1, const float* __restrict__ rv1,
                        const float* __restrict__ g2, const float* __restrict__ be2,
                        const float* __restrict__ rm2, const float* __restrict__ rv2,
                        const float* __restrict__ W1)
{
    int t = threadIdx.x;
    bool s64 = (((const int*)snv)[1] == 0);
    bool d64 = (((const int*)dnv)[1] == 0);
    __shared__ int sc[NSEG], dc[NSEG];
    if (t < NSEG) {
        sc[t] = read_count(snv, t, s64);
        dc[t] = read_count(dnv, t, d64);
    }
    __syncthreads();
    if (t == 0) {
        int ss = 0, dd = 0;
        for (int i = 0; i < NSEG; i++) {
            g_soff[i] = ss; g_doff[i] = dd;
            g_scnt[i] = sc[i]; g_dcnt[i] = dc[i];
            ss += sc[i]; dd += dc[i];
        }
        g_soff[NSEG] = ss; g_doff[NSEG] = dd;
    }
    {
        float s1v = g1[t] * rsqrtf(rv1[t] + 1e-5f);
        g_s1[t] = s1v; g_t1[t] = be1[t] - rm1[t] * s1v;
        float s2v = g2[t] * rsqrtf(rv2[t] + 1e-5f);
        g_s2[t] = s2v; g_t2[t] = be2[t] - rm2[t] * s2v;
    }
    if (t < 128) g_bqp[t] = bq[permc(t)];
    g_bkvp[t] = (t < 128) ? bk[permc(t)] : bv[permc(t - 128)];
    {   // b1' = b1 + W1b @ bm
        float acc = b1[t];
        const float* wrow = W1 + t * 384 + 256;
        #pragma unroll 8
        for (int j = 0; j < 128; j++) acc += wrow[j] * bm[j];
        g_b1p[t] = acc;
    }
}

// ---------------------- fp32 -> bf16 activation convert --------------------
__global__ void k_convert(const float* __restrict__ s, const float* __restrict__ d)
{
    int i = blockIdx.x * blockDim.x + threadIdx.x;   // over TOTAL*256/8
    const float4* s4 = (const float4*)s;
    const float4* d4 = (const float4*)d;
    float4 a = s4[2 * i], b = s4[2 * i + 1];
    uint4 o;
    o.x = pk(a.x, a.y); o.y = pk(a.z, a.w); o.z = pk(b.x, b.y); o.w = pk(b.z, b.w);
    ((uint4*)g_csrc)[i] = o;
    a = d4[2 * i]; b = d4[2 * i + 1];
    o.x = pk(a.x, a.y); o.y = pk(a.z, a.w); o.z = pk(b.x, b.y); o.w = pk(b.z, b.w);
    ((uint4*)g_cdst)[i] = o;
}

// ------------------------ weight conversion + permute ----------------------
__global__ void k_prep(const float* __restrict__ Wk, const float* __restrict__ Wv,
                       const float* __restrict__ Wq, const float* __restrict__ W1,
                       const float* __restrict__ W2)
{
    int i = blockIdx.x * blockDim.x + threadIdx.x;   // 65536 threads
    {
        int n = i >> 8, k = i & 255;
        float v = (n < 128) ? Wk[permc(n) * 256 + k] : Wv[permc(n - 128) * 256 + k];
        g_Wkv[i] = __float2bfloat16(v);
    }
    if (i < 128 * 256) {
        int n = i >> 8, k = i & 255;
        g_Wq[i] = __float2bfloat16(Wq[permc(n) * 256 + k]);
    }
    {
        int n = i >> 8, k = i & 255;
        g_W1a[i] = __float2bfloat16(W1[n * 384 + k]);
    }
    g_W2b[i] = __float2bfloat16(W2[i]);
}

// ------------------- W1bp = (W1b @ Wm), head-major columns -----------------
// 16 blocks x 256 thr. Block b owns 16 rows of W1b; each thread owns one Wm
// column (coalesced) and 8 output rows -> 8 FMAs per Wm load, 8x less L2
// traffic than one-row-per-block, MLP~8 via unrolled j loop.
__global__ void k_w1bp(const float* __restrict__ W1, const float* __restrict__ Wm)
{
    __shared__ float w1s[16][128];
    const int b = blockIdx.x, t = threadIdx.x;
    const int r0 = b * 16;
    #pragma unroll
    for (int i = 0; i < 8; i++) {
        int idx = t + i * 256;                        // 2048 = 16*128
        int rr = idx >> 7, cc = idx & 127;
        w1s[rr][cc] = W1[(r0 + rr) * 384 + 256 + cc];
    }
    __syncthreads();
    const int half = t >> 7;                          // 0/1 -> rows 0-7 / 8-15
    const int cp = t & 127;                           // Wm column (coalesced)
    const float* wmc = Wm + cp;
    float acc[8] = {};
    #pragma unroll 8
    for (int j = 0; j < 128; j++) {
        float wv = wmc[j * 128];
        #pragma unroll
        for (int r = 0; r < 8; r++)
            acc[r] += w1s[half * 8 + r][j] * wv;
    }
    const int co = (cp & 3) * 32 + (cp >> 2);         // head-major position of cp
    #pragma unroll
    for (int r = 0; r < 8; r++)
        g_W1bp[(r0 + half * 8 + r) * 128 + co] = __float2bfloat16(acc[r]);
}

// ------------------------------ bf16 MMA GEMM ------------------------------
// C[M,N] = A[M,K](bf16) @ W[N,K](bf16)^T + epilogue. 128x64 block, BK=32,
// 256 thr = 8 warps (4m x 2n), warp tile 32x32 (2x4 m16n8k16 frags).
// 3-stage cp.async pipeline: one __syncthreads per k-iter, 2 stages in flight.
// MODE 0: acc + bias     MODE 1: relu((acc+aux)*s+t)   MODE 2: (acc+bias)*s+t+aux
template<int MODE, bool OBF>
__global__ __launch_bounds__(256) void k_gemm(
    const __nv_bfloat16* __restrict__ A, int K,
    const __nv_bfloat16* __restrict__ W,
    const float* __restrict__ bias,
    void* __restrict__ Cv, int N,
    const float* __restrict__ aux, int auxLd,
    const float* __restrict__ sbn, const float* __restrict__ tbn)
{
    constexpr int ST = 3;
    __shared__ __align__(16) __nv_bfloat16 As[ST][128 * 32];
    __shared__ __align__(16) __nv_bfloat16 Bs[ST][64 * 32];
    const int t = threadIdx.x, lane = t & 31, w = t >> 5;
    const int mw = w >> 1, nw = w & 1;
    const int m0 = blockIdx.x * 128, n0 = blockIdx.y * 64;

    const int rA = t >> 2, kc = t & 3;
    const int swz = kc ^ ((rA >> 1) & 3);
    const __nv_bfloat16* Ag0 = A + (size_t)(m0 + rA) * K + kc * 8;
    const __nv_bfloat16* Ag1 = Ag0 + (size_t)64 * K;
    const __nv_bfloat16* Wg  = W + (size_t)(n0 + rA) * K + kc * 8;
    const int oA0 = (rA * 4 + swz) * 8;              // element offsets in a stage
    const int oA1 = ((rA + 64) * 4 + swz) * 8;
    const int oB  = (rA * 4 + swz) * 8;
    const uint32_t baseA = (uint32_t)__cvta_generic_to_shared(As);
    const uint32_t baseB = (uint32_t)__cvta_generic_to_shared(Bs);

    const int nIter = K >> 5;

    // prologue: fill stages 0..ST-2
    #pragma unroll
    for (int s = 0; s < ST - 1; s++) {
        if (s < nIter) {
            cpa16(baseA + (s * 128 * 32 + oA0) * 2, Ag0 + s * 32);
            cpa16(baseA + (s * 128 * 32 + oA1) * 2, Ag1 + s * 32);
            cpa16(baseB + (s * 64 * 32 + oB) * 2,  Wg  + s * 32);
        }
        cpa_commit();
    }

    float acc[2][4][4] = {};
    int stage = 0;
    for (int i = 0; i < nIter; i++) {
        cpa_wait<ST - 2>();          // stage i resident
        __syncthreads();             // all writers of stage i done; all readers of
                                     // stage (i+2)%ST (read at iter i-1) passed
        {
            const int nx = i + ST - 1;
            if (nx < nIter) {
                const int sb = (stage + ST - 1) % ST;
                cpa16(baseA + (sb * 128 * 32 + oA0) * 2, Ag0 + nx * 32);
                cpa16(baseA + (sb * 128 * 32 + oA1) * 2, Ag1 + nx * 32);
                cpa16(baseB + (sb * 64 * 32 + oB) * 2,  Wg  + nx * 32);
            }
            cpa_commit();
        }
        const uint32_t bA = baseA + stage * (128 * 32 * 2);
        const uint32_t bB = baseB + stage * (64 * 32 * 2);
        #pragma unroll
        for (int kk = 0; kk < 2; kk++) {
            uint32_t af[2][4];
            #pragma unroll
            for (int f = 0; f < 2; f++) {
                int row = mw * 32 + f * 16 + (lane & 15);
                int c8 = (kk * 2 + (lane >> 4)) ^ ((row >> 1) & 3);
                ldsm4(af[f][0], af[f][1], af[f][2], af[f][3],
                      bA + (row * 4 + c8) * 16);
            }
            uint32_t bfr[2][4];
            #pragma unroll
            for (int p = 0; p < 2; p++) {
                int row = nw * 32 + p * 16 + (lane & 7) + ((lane >> 4) << 3);
                int c8 = (kk * 2 + ((lane >> 3) & 1)) ^ ((row >> 1) & 3);
                ldsm4(bfr[p][0], bfr[p][1], bfr[p][2], bfr[p][3],
                      bB + (row * 4 + c8) * 16);
            }
            #pragma unroll
            for (int f = 0; f < 2; f++)
                #pragma unroll
                for (int n = 0; n < 4; n++)
                    mma_bf16(acc[f][n], af[f], &bfr[n >> 1][(n & 1) * 2]);
        }
        stage = (stage + 1) % ST;
    }

    const int er = m0 + mw * 32 + (lane >> 2);
    const int ec = n0 + nw * 32 + (lane & 3) * 2;
    #pragma unroll
    for (int f = 0; f < 2; f++)
        #pragma unroll
        for (int n = 0; n < 4; n++)
            #pragma unroll
            for (int half = 0; half < 2; half++) {
                int r = er + f * 16 + half * 8;
                int c = ec + n * 8;
                float x0 = acc[f][n][half * 2], x1 = acc[f][n][half * 2 + 1];
                if (MODE == 0) {
                    x0 += bias[c]; x1 += bias[c + 1];
                } else if (MODE == 1) {
                    x0 += aux[(size_t)r * auxLd + c];
                    x1 += aux[(size_t)r * auxLd + c + 1];
                    x0 = fmaxf(x0 * sbn[c] + tbn[c], 0.f);
                    x1 = fmaxf(x1 * sbn[c + 1] + tbn[c + 1], 0.f);
                } else {
                    x0 = (x0 + bias[c]) * sbn[c] + tbn[c] + aux[(size_t)r * auxLd + c];
                    x1 = (x1 + bias[c + 1]) * sbn[c + 1] + tbn[c + 1] +
                         aux[(size_t)r * auxLd + c + 1];
                }
                if (OBF) {
                    __nv_bfloat162 h = __floats2bfloat162_rn(x0, x1);
                    *(__nv_bfloat162*)((__nv_bfloat16*)Cv + (size_t)r * N + c) = h;
                } else {
                    *(float2*)((float*)Cv + (size_t)r * N + c) = make_float2(x0, x1);
                }
            }
}

// ------------------------------- Attention ---------------------------------
// Block: 64 dst rows of one segment; 8 warps = 4 heads x 2 q-halves.
// Flash-style: S frags (fp32) -> ex2 -> in-register bf16 A frags -> PV mma,
// V B-frags via ldmatrix.trans straight from the row-major kv tile.
__global__ __launch_bounds__(256) void k_attn()
{
    __shared__ __align__(16) __nv_bfloat16 qs[64 * 128];
    __shared__ __align__(16) __nv_bfloat16 ks[32 * 256];
    const int b = blockIdx.y, q0 = blockIdx.x * 64;
    const int nd = g_dcnt[b];
    if (q0 >= nd) return;
    const int ns = g_scnt[b], soff = g_soff[b], doff = g_doff[b];
    const int nQ = min(64, nd - q0);
    const int t = threadIdx.x, lane = t & 31, w = t >> 5;
    const int h = w & 3, qh = w >> 2;

    #pragma unroll
    for (int i = 0; i < 4; i++) {
        int idx = t + i * 256;
        int row = idx >> 4, c = idx & 15;
        uint4 v = make_uint4(0, 0, 0, 0);
        if (row < nQ)
            v = *(const uint4*)(g_q + (size_t)(doff + q0 + row) * 128 + c * 8);
        *(uint4*)(qs + (row * 16 + (c ^ (row & 7))) * 8) = v;
    }

    const uint32_t baseQ = (uint32_t)__cvta_generic_to_shared(qs);
    const uint32_t baseK = (uint32_t)__cvta_generic_to_shared(ks);
    float acc[2][4][4] = {};
    float den[2][2] = {};
    const float sc2 = 0.25504167f;   // log2(e)/sqrt(32)

    const int nT = (ns + 31) >> 5;
    for (int tt = 0; tt < nT; tt++) {
        const int s0 = tt * 32;
        __syncthreads();
        #pragma unroll
        for (int i = 0; i < 4; i++) {
            int idx = t + i * 256;
            int row = idx >> 5, c = idx & 31;
            int gr = soff + s0 + row; if (gr >= TOTAL) gr = TOTAL - 1;
            uint4 v = *(const uint4*)(g_kv + (size_t)gr * 256 + c * 8);
            *(uint4*)(ks + (row * 32 + (c ^ (row & 7))) * 8) = v;
        }
        __syncthreads();

        // ---- S = Q K^T (per head, K=32) ----
        float S[2][4][4] = {};
        #pragma unroll
        for (int kk = 0; kk < 2; kk++) {
            uint32_t af[2][4];
            #pragma unroll
            for (int f = 0; f < 2; f++) {
                int row = qh * 32 + f * 16 + (lane & 15);
                int c8 = (h * 4 + kk * 2 + (lane >> 4)) ^ (row & 7);
                ldsm4(af[f][0], af[f][1], af[f][2], af[f][3],
                      baseQ + (row * 16 + c8) * 16);
            }
            uint32_t bk2[2][4];
            #pragma unroll
            for (int p = 0; p < 2; p++) {
                int row = p * 16 + (lane & 7) + ((lane >> 4) << 3);
                int c8 = (h * 4 + kk * 2 + ((lane >> 3) & 1)) ^ (row & 7);
                ldsm4(bk2[p][0], bk2[p][1], bk2[p][2], bk2[p][3],
                      baseK + (row * 32 + c8) * 16);
            }
            #pragma unroll
            for (int f = 0; f < 2; f++)
                #pragma unroll
                for (int n = 0; n < 4; n++)
                    mma_bf16(S[f][n], af[f], &bk2[n >> 1][(n & 1) * 2]);
        }

        // ---- exp + mask + den, pack P into A fragments ----
        uint32_t Ap[2][2][4];
        #pragma unroll
        for (int f = 0; f < 2; f++) {
            float d0 = 0.f, d1 = 0.f;
            #pragma unroll
            for (int n = 0; n < 4; n++) {
                int cb = s0 + n * 8 + (lane & 3) * 2;
                float e0 = ex2(S[f][n][0] * sc2); if (cb >= ns) e0 = 0.f;
                float e1 = ex2(S[f][n][1] * sc2); if (cb + 1 >= ns) e1 = 0.f;
                float e2 = ex2(S[f][n][2] * sc2); if (cb >= ns) e2 = 0.f;
                float e3 = ex2(S[f][n][3] * sc2); if (cb + 1 >= ns) e3 = 0.f;
                d0 += e0 + e1; d1 += e2 + e3;
                Ap[f][n >> 1][(n & 1) * 2]     = pk(e0, e1);
                Ap[f][n >> 1][(n & 1) * 2 + 1] = pk(e2, e3);
            }
            den[f][0] += d0; den[f][1] += d1;
        }

        // ---- O += P V (V B-frags via ldmatrix.trans) ----
        #pragma unroll
        for (int kk = 0; kk < 2; kk++) {
            uint32_t bv[2][4];
            #pragma unroll
            for (int p = 0; p < 2; p++) {
                int row = kk * 16 + (lane & 15);
                int c8 = (16 + h * 4 + p * 2 + (lane >> 4)) ^ (row & 7);
                ldsm4t(bv[p][0], bv[p][1], bv[p][2], bv[p][3],
                       baseK + (row * 32 + c8) * 16);
            }
            #pragma unroll
            for (int f = 0; f < 2; f++)
                #pragma unroll
                for (int n = 0; n < 4; n++)
                    mma_bf16(acc[f][n], Ap[f][kk], &bv[n >> 1][(n & 1) * 2]);
        }
    }

    #pragma unroll
    for (int f = 0; f < 2; f++)
        #pragma unroll
        for (int u = 0; u < 2; u++) {
            float v = den[f][u];
            v += __shfl_xor_sync(0xffffffffu, v, 1);
            v += __shfl_xor_sync(0xffffffffu, v, 2);
            den[f][u] = 1.f / v;
        }

    #pragma unroll
    for (int f = 0; f < 2; f++)
        #pragma unroll
        for (int n = 0; n < 4; n++)
            #pragma unroll
            for (int half = 0; half < 2; half++) {
                int rl = qh * 32 + f * 16 + (lane >> 2) + half * 8;
                if (rl < nQ) {
                    float inv = den[f][half];
                    __nv_bfloat162 o = __floats2bfloat162_rn(
                        acc[f][n][half * 2] * inv, acc[f][n][half * 2 + 1] * inv);
                    *(__nv_bfloat162*)(g_msg + (size_t)(doff + q0 + rl) * 128 +
                                       h * 32 + n * 8 + (lane & 3) * 2) = o;
                }
            }
}

// ------------------------------- launcher ----------------------------------
extern "C" void kernel_launch(void* const* d_in, const int* in_sizes, int n_in,
                              void* d_out, int out_size)
{
    const float* src_h = (const float*)d_in[0];
    const float* dst_h = (const float*)d_in[1];
    const void*  snv   = d_in[2];
    const void*  dnv   = d_in[3];
    const float* Wq = (const float*)d_in[4];  const float* bq = (const float*)d_in[5];
    const float* Wk = (const float*)d_in[6];  const float* bk = (const float*)d_in[7];
    const float* Wv = (const float*)d_in[8];  const float* bv = (const float*)d_in[9];
    const float* Wm = (const float*)d_in[10]; const float* bm = (const float*)d_in[11];
    const float* W1 = (const float*)d_in[12]; const float* b1 = (const float*)d_in[13];
    const float* g1 = (const float*)d_in[14]; const float* be1 = (const float*)d_in[15];
    const float* rm1 = (const float*)d_in[16]; const float* rv1 = (const float*)d_in[17];
    const float* W2 = (const float*)d_in[18]; const float* b2 = (const float*)d_in[19];
    const float* g2 = (const float*)d_in[20]; const float* be2 = (const float*)d_in[21];
    const float* rm2 = (const float*)d_in[22]; const float* rv2 = (const float*)d_in[23];
    float* out = (float*)d_out;

    __nv_bfloat16 *p_csrc, *p_cdst, *p_kv, *p_q, *p_msg, *p_x1;
    __nv_bfloat16 *p_Wkv, *p_Wq, *p_W1a, *p_W1bp, *p_W2b;
    float *p_y1a, *p_bkvp, *p_bqp, *p_b1p, *p_s1, *p_t1, *p_s2, *p_t2;
    cudaGetSymbolAddress((void**)&p_csrc, g_csrc);
    cudaGetSymbolAddress((void**)&p_cdst, g_cdst);
    cudaGetSymbolAddress((void**)&p_kv, g_kv);
    cudaGetSymbolAddress((void**)&p_q, g_q);
    cudaGetSymbolAddress((void**)&p_y1a, g_y1a);
    cudaGetSymbolAddress((void**)&p_msg, g_msg);
    cudaGetSymbolAddress((void**)&p_x1, g_x1);
    cudaGetSymbolAddress((void**)&p_Wkv, g_Wkv);
    cudaGetSymbolAddress((void**)&p_Wq, g_Wq);
    cudaGetSymbolAddress((void**)&p_W1a, g_W1a);
    cudaGetSymbolAddress((void**)&p_W1bp, g_W1bp);
    cudaGetSymbolAddress((void**)&p_W2b, g_W2b);
    cudaGetSymbolAddress((void**)&p_bkvp, g_bkvp);
    cudaGetSymbolAddress((void**)&p_bqp, g_bqp);
    cudaGetSymbolAddress((void**)&p_b1p, g_b1p);
    cudaGetSymbolAddress((void**)&p_s1, g_s1);
    cudaGetSymbolAddress((void**)&p_t1, g_t1);
    cudaGetSymbolAddress((void**)&p_s2, g_s2);
    cudaGetSymbolAddress((void**)&p_t2, g_t2);

    k_setup<<<1, 256>>>(snv, dnv, bq, bk, bv, bm, b1, g1, be1, rm1, rv1,
                        g2, be2, rm2, rv2, W1);
    k_convert<<<TOTAL * 256 / 8 / 256, 256>>>(src_h, dst_h);
    k_prep<<<256, 256>>>(Wk, Wv, Wq, W1, W2);
    k_w1bp<<<16, 256>>>(W1, Wm);

    // G1: kv = src @ [Wk;Wv]'.T    (bf16 out, head-major)
    k_gemm<0, true><<<dim3(192, 4), 256>>>(p_csrc, 256, p_Wkv, p_bkvp,
                                           p_kv, 256, nullptr, 0, nullptr, nullptr);
    // G2a: q = dst @ Wq'.T         (bf16 out, head-major)
    k_gemm<0, true><<<dim3(192, 2), 256>>>(p_cdst, 256, p_Wq, p_bqp,
                                           p_q, 128, nullptr, 0, nullptr, nullptr);
    // G2b: y1a = dst @ W1a.T + b1' (fp32 out)
    k_gemm<0, false><<<dim3(192, 4), 256>>>(p_cdst, 256, p_W1a, p_b1p,
                                            p_y1a, 256, nullptr, 0, nullptr, nullptr);
    // A: msg = attention(q, k, v)  (bf16 out, head-major)
    k_attn<<<dim3(8, NSEG), 256>>>();
    // G3: x1 = relu((msg @ W1bp'.T + y1a) * s1 + t1)  (bf16 out)
    k_gemm<1, true><<<dim3(192, 4), 256>>>(p_msg, 128, p_W1bp, nullptr,
                                           p_x1, 256, p_y1a, 256, p_s1, p_t1);
    // G4: out = (x1 @ W2.T + b2) * s2 + t2 + dst_h    (fp32 out)
    k_gemm<2, false><<<dim3(192, 4), 256>>>(p_x1, 256, p_W2b, b2,
                                            out, 256, dst_h, 256, p_s2, p_t2);
}

// round 11
// speedup vs baseline: 1.0174x; 1.0174x over previous
#include <cuda_runtime.h>
#include <cuda_bf16.h>
#include <cstdint>

#define TOTAL 24576
#define NSEG  64

// ------------------------- device scratch (static) -------------------------
__device__ __nv_bfloat16 g_csrc[TOTAL * 256];
__device__ __nv_bfloat16 g_cdst[TOTAL * 256];
__device__ __nv_bfloat16 g_kv  [TOTAL * 256];   // head-major k|v, bf16
__device__ __nv_bfloat16 g_q   [TOTAL * 128];   // head-major q, bf16
__device__ float         g_y1a [TOTAL * 256];   // dst_h @ W1a.T + b1'
__device__ __nv_bfloat16 g_msg [TOTAL * 128];   // head-major attention out
__device__ __nv_bfloat16 g_x1  [TOTAL * 256];
__device__ __nv_bfloat16 g_Wkv [256 * 256];
__device__ __nv_bfloat16 g_Wq  [128 * 256];
__device__ __nv_bfloat16 g_W1a [256 * 256];
__device__ __nv_bfloat16 g_W1bp[256 * 128];
__device__ __nv_bfloat16 g_W2b [256 * 256];
__device__ float g_bkvp[256], g_bqp[128], g_b1p[256];
__device__ float g_s1[256], g_t1[256], g_s2[256], g_t2[256];
__device__ int g_soff[NSEG + 1], g_doff[NSEG + 1], g_scnt[NSEG], g_dcnt[NSEG];

__device__ __forceinline__ int permc(int n) { return (n & 31) * 4 + (n >> 5); }

// ------------------------------ PTX helpers --------------------------------
__device__ __forceinline__ void ldsm4(uint32_t& r0, uint32_t& r1, uint32_t& r2,
                                      uint32_t& r3, uint32_t a) {
    asm volatile("ldmatrix.sync.aligned.m8n8.x4.shared.b16 {%0,%1,%2,%3}, [%4];"
                 : "=r"(r0), "=r"(r1), "=r"(r2), "=r"(r3) : "r"(a));
}
__device__ __forceinline__ void ldsm4t(uint32_t& r0, uint32_t& r1, uint32_t& r2,
                                       uint32_t& r3, uint32_t a) {
    asm volatile("ldmatrix.sync.aligned.m8n8.x4.trans.shared.b16 {%0,%1,%2,%3}, [%4];"
                 : "=r"(r0), "=r"(r1), "=r"(r2), "=r"(r3) : "r"(a));
}
__device__ __forceinline__ void mma_bf16(float c[4], const uint32_t a[4],
                                         const uint32_t b[2]) {
    asm volatile(
        "mma.sync.aligned.m16n8k16.row.col.f32.bf16.bf16.f32 "
        "{%0,%1,%2,%3},{%4,%5,%6,%7},{%8,%9},{%0,%1,%2,%3};"
        : "+f"(c[0]), "+f"(c[1]), "+f"(c[2]), "+f"(c[3])
        : "r"(a[0]), "r"(a[1]), "r"(a[2]), "r"(a[3]), "r"(b[0]), "r"(b[1]));
}
__device__ __forceinline__ float ex2(float x) {
    float r; asm("ex2.approx.f32 %0, %1;" : "=f"(r) : "f"(x)); return r;
}
__device__ __forceinline__ uint32_t pk(float a, float b) {
    __nv_bfloat162 v = __floats2bfloat162_rn(a, b);
    return *reinterpret_cast<uint32_t*>(&v);
}
__device__ __forceinline__ void cpa16(uint32_t s, const void* g) {
    asm volatile("cp.async.cg.shared.global [%0], [%1], 16;" :: "r"(s), "l"(g));
}
__device__ __forceinline__ void cpa_commit() {
    asm volatile("cp.async.commit_group;" ::: "memory");
}
template<int N>
__device__ __forceinline__ void cpa_wait() {
    asm volatile("cp.async.wait_group %0;" :: "n"(N) : "memory");
}

// ------------------------------- K0: setup ---------------------------------
__device__ __forceinline__ int read_count(const void* p, int i, bool is64) {
    if (is64) return (int)((const long long*)p)[i];
    return ((const int*)p)[i];
}

__global__ void k_setup(const void* snv, const void* dnv,
                        const float* __restrict__ bq, const float* __restrict__ bk,
                        const float* __restrict__ bv, const float* __restrict__ bm,
                        const float* __restrict__ b1,
                        const float* __restrict__ g1, const float* __restrict__ be1,
                        const float* __restrict__ rm1, const float* __restrict__ rv1,
                        const float* __restrict__ g2, const float* __restrict__ be2,
                        const float* __restrict__ rm2, const float* __restrict__ rv2,
                        const float* __restrict__ W1)
{
    int t = threadIdx.x;
    bool s64 = (((const int*)snv)[1] == 0);
    bool d64 = (((const int*)dnv)[1] == 0);
    __shared__ int sc[NSEG], dc[NSEG];
    if (t < NSEG) {
        sc[t] = read_count(snv, t, s64);
        dc[t] = read_count(dnv, t, d64);
    }
    __syncthreads();
    if (t == 0) {
        int ss = 0, dd = 0;
        for (int i = 0; i < NSEG; i++) {
            g_soff[i] = ss; g_doff[i] = dd;
            g_scnt[i] = sc[i]; g_dcnt[i] = dc[i];
            ss += sc[i]; dd += dc[i];
        }
        g_soff[NSEG] = ss; g_doff[NSEG] = dd;
    }
    {
        float s1v = g1[t] * rsqrtf(rv1[t] + 1e-5f);
        g_s1[t] = s1v; g_t1[t] = be1[t] - rm1[t] * s1v;
        float s2v = g2[t] * rsqrtf(rv2[t] + 1e-5f);
        g_s2[t] = s2v; g_t2[t] = be2[t] - rm2[t] * s2v;
    }
    if (t < 128) g_bqp[t] = bq[permc(t)];
    g_bkvp[t] = (t < 128) ? bk[permc(t)] : bv[permc(t - 128)];
    {   // b1' = b1 + W1b @ bm
        float acc = b1[t];
        const float* wrow = W1 + t * 384 + 256;
        #pragma unroll 8
        for (int j = 0; j < 128; j++) acc += wrow[j] * bm[j];
        g_b1p[t] = acc;
    }
}

// ---------------------- fp32 -> bf16 activation convert --------------------
__global__ void k_convert(const float* __restrict__ s, const float* __restrict__ d)
{
    int i = blockIdx.x * blockDim.x + threadIdx.x;   // over TOTAL*256/8
    const float4* s4 = (const float4*)s;
    const float4* d4 = (const float4*)d;
    float4 a = s4[2 * i], b = s4[2 * i + 1];
    uint4 o;
    o.x = pk(a.x, a.y); o.y = pk(a.z, a.w); o.z = pk(b.x, b.y); o.w = pk(b.z, b.w);
    ((uint4*)g_csrc)[i] = o;
    a = d4[2 * i]; b = d4[2 * i + 1];
    o.x = pk(a.x, a.y); o.y = pk(a.z, a.w); o.z = pk(b.x, b.y); o.w = pk(b.z, b.w);
    ((uint4*)g_cdst)[i] = o;
}

// ------------------------ weight conversion + permute ----------------------
__global__ void k_prep(const float* __restrict__ Wk, const float* __restrict__ Wv,
                       const float* __restrict__ Wq, const float* __restrict__ W1,
                       const float* __restrict__ W2)
{
    int i = blockIdx.x * blockDim.x + threadIdx.x;   // 65536 threads
    {
        int n = i >> 8, k = i & 255;
        float v = (n < 128) ? Wk[permc(n) * 256 + k] : Wv[permc(n - 128) * 256 + k];
        g_Wkv[i] = __float2bfloat16(v);
    }
    if (i < 128 * 256) {
        int n = i >> 8, k = i & 255;
        g_Wq[i] = __float2bfloat16(Wq[permc(n) * 256 + k]);
    }
    {
        int n = i >> 8, k = i & 255;
        g_W1a[i] = __float2bfloat16(W1[n * 384 + k]);
    }
    g_W2b[i] = __float2bfloat16(W2[i]);
}

// ------------------- W1bp = (W1b @ Wm), head-major columns -----------------
// 2D-tiled: grid (32 row-tiles x 4 col-tiles) = 128 blocks x 256 thr.
// Block owns 8 rows x 32 cols. Warp = one row x 32 cols: Wm[j, colrange] is
// one coalesced 128B line per j, shared across the 8 warps via L1; w1s[row][j]
// is warp-uniform (smem broadcast). L2 traffic 2MB, full-SM parallelism.
__global__ void k_w1bp(const float* __restrict__ W1, const float* __restrict__ Wm)
{
    __shared__ float w1s[8][128];
    const int rb = blockIdx.x, cb = blockIdx.y, t = threadIdx.x;
    const int r0 = rb * 8;
    #pragma unroll
    for (int i = 0; i < 4; i++) {
        int idx = t + i * 256;                        // 1024 = 8*128
        int rr = idx >> 7, cc = idx & 127;
        w1s[rr][cc] = W1[(r0 + rr) * 384 + 256 + cc];
    }
    __syncthreads();
    const int row = t >> 5;                           // 0..7 (warp id)
    const int cp = cb * 32 + (t & 31);                // Wm column (coalesced/warp)
    const float* wmc = Wm + cp;
    float acc = 0.f;
    #pragma unroll 8
    for (int j = 0; j < 128; j++)
        acc += w1s[row][j] * wmc[j * 128];
    const int co = (cp & 3) * 32 + (cp >> 2);         // head-major position of cp
    g_W1bp[(r0 + row) * 128 + co] = __float2bfloat16(acc);
}

// ------------------------------ bf16 MMA GEMM ------------------------------
// C[M,N] = A[M,K](bf16) @ W[N,K](bf16)^T + epilogue. 128x64 block, BK=32,
// 256 thr = 8 warps (4m x 2n), warp tile 32x32 (2x4 m16n8k16 frags).
// 3-stage cp.async pipeline: one __syncthreads per k-iter, 2 stages in flight.
// MODE 0: acc + bias     MODE 1: relu((acc+aux)*s+t)   MODE 2: (acc+bias)*s+t+aux
template<int MODE, bool OBF>
__global__ __launch_bounds__(256) void k_gemm(
    const __nv_bfloat16* __restrict__ A, int K,
    const __nv_bfloat16* __restrict__ W,
    const float* __restrict__ bias,
    void* __restrict__ Cv, int N,
    const float* __restrict__ aux, int auxLd,
    const float* __restrict__ sbn, const float* __restrict__ tbn)
{
    constexpr int ST = 3;
    __shared__ __align__(16) __nv_bfloat16 As[ST][128 * 32];
    __shared__ __align__(16) __nv_bfloat16 Bs[ST][64 * 32];
    const int t = threadIdx.x, lane = t & 31, w = t >> 5;
    const int mw = w >> 1, nw = w & 1;
    const int m0 = blockIdx.x * 128, n0 = blockIdx.y * 64;

    const int rA = t >> 2, kc = t & 3;
    const int swz = kc ^ ((rA >> 1) & 3);
    const __nv_bfloat16* Ag0 = A + (size_t)(m0 + rA) * K + kc * 8;
    const __nv_bfloat16* Ag1 = Ag0 + (size_t)64 * K;
    const __nv_bfloat16* Wg  = W + (size_t)(n0 + rA) * K + kc * 8;
    const int oA0 = (rA * 4 + swz) * 8;              // element offsets in a stage
    const int oA1 = ((rA + 64) * 4 + swz) * 8;
    const int oB  = (rA * 4 + swz) * 8;
    const uint32_t baseA = (uint32_t)__cvta_generic_to_shared(As);
    const uint32_t baseB = (uint32_t)__cvta_generic_to_shared(Bs);

    const int nIter = K >> 5;

    // prologue: fill stages 0..ST-2
    #pragma unroll
    for (int s = 0; s < ST - 1; s++) {
        if (s < nIter) {
            cpa16(baseA + (s * 128 * 32 + oA0) * 2, Ag0 + s * 32);
            cpa16(baseA + (s * 128 * 32 + oA1) * 2, Ag1 + s * 32);
            cpa16(baseB + (s * 64 * 32 + oB) * 2,  Wg  + s * 32);
        }
        cpa_commit();
    }

    float acc[2][4][4] = {};
    int stage = 0;
    for (int i = 0; i < nIter; i++) {
        cpa_wait<ST - 2>();          // stage i resident
        __syncthreads();             // all writers of stage i done; all readers of
                                     // stage (i+2)%ST (read at iter i-1) passed
        {
            const int nx = i + ST - 1;
            if (nx < nIter) {
                const int sb = (stage + ST - 1) % ST;
                cpa16(baseA + (sb * 128 * 32 + oA0) * 2, Ag0 + nx * 32);
                cpa16(baseA + (sb * 128 * 32 + oA1) * 2, Ag1 + nx * 32);
                cpa16(baseB + (sb * 64 * 32 + oB) * 2,  Wg  + nx * 32);
            }
            cpa_commit();
        }
        const uint32_t bA = baseA + stage * (128 * 32 * 2);
        const uint32_t bB = baseB + stage * (64 * 32 * 2);
        #pragma unroll
        for (int kk = 0; kk < 2; kk++) {
            uint32_t af[2][4];
            #pragma unroll
            for (int f = 0; f < 2; f++) {
                int row = mw * 32 + f * 16 + (lane & 15);
                int c8 = (kk * 2 + (lane >> 4)) ^ ((row >> 1) & 3);
                ldsm4(af[f][0], af[f][1], af[f][2], af[f][3],
                      bA + (row * 4 + c8) * 16);
            }
            uint32_t bfr[2][4];
            #pragma unroll
            for (int p = 0; p < 2; p++) {
                int row = nw * 32 + p * 16 + (lane & 7) + ((lane >> 4) << 3);
                int c8 = (kk * 2 + ((lane >> 3) & 1)) ^ ((row >> 1) & 3);
                ldsm4(bfr[p][0], bfr[p][1], bfr[p][2], bfr[p][3],
                      bB + (row * 4 + c8) * 16);
            }
            #pragma unroll
            for (int f = 0; f < 2; f++)
                #pragma unroll
                for (int n = 0; n < 4; n++)
                    mma_bf16(acc[f][n], af[f], &bfr[n >> 1][(n & 1) * 2]);
        }
        stage = (stage + 1) % ST;
    }

    const int er = m0 + mw * 32 + (lane >> 2);
    const int ec = n0 + nw * 32 + (lane & 3) * 2;
    #pragma unroll
    for (int f = 0; f < 2; f++)
        #pragma unroll
        for (int n = 0; n < 4; n++)
            #pragma unroll
            for (int half = 0; half < 2; half++) {
                int r = er + f * 16 + half * 8;
                int c = ec + n * 8;
                float x0 = acc[f][n][half * 2], x1 = acc[f][n][half * 2 + 1];
                if (MODE == 0) {
                    x0 += bias[c]; x1 += bias[c + 1];
                } else if (MODE == 1) {
                    x0 += aux[(size_t)r * auxLd + c];
                    x1 += aux[(size_t)r * auxLd + c + 1];
                    x0 = fmaxf(x0 * sbn[c] + tbn[c], 0.f);
                    x1 = fmaxf(x1 * sbn[c + 1] + tbn[c + 1], 0.f);
                } else {
                    x0 = (x0 + bias[c]) * sbn[c] + tbn[c] + aux[(size_t)r * auxLd + c];
                    x1 = (x1 + bias[c + 1]) * sbn[c + 1] + tbn[c + 1] +
                         aux[(size_t)r * auxLd + c + 1];
                }
                if (OBF) {
                    __nv_bfloat162 h = __floats2bfloat162_rn(x0, x1);
                    *(__nv_bfloat162*)((__nv_bfloat16*)Cv + (size_t)r * N + c) = h;
                } else {
                    *(float2*)((float*)Cv + (size_t)r * N + c) = make_float2(x0, x1);
                }
            }
}

// ------------------------------- Attention ---------------------------------
// Block: 64 dst rows of one segment; 8 warps = 4 heads x 2 q-halves.
// Flash-style: S frags (fp32) -> ex2 -> in-register bf16 A frags -> PV mma,
// V B-frags via ldmatrix.trans straight from the row-major kv tile.
__global__ __launch_bounds__(256) void k_attn()
{
    __shared__ __align__(16) __nv_bfloat16 qs[64 * 128];
    __shared__ __align__(16) __nv_bfloat16 ks[32 * 256];
    const int b = blockIdx.y, q0 = blockIdx.x * 64;
    const int nd = g_dcnt[b];
    if (q0 >= nd) return;
    const int ns = g_scnt[b], soff = g_soff[b], doff = g_doff[b];
    const int nQ = min(64, nd - q0);
    const int t = threadIdx.x, lane = t & 31, w = t >> 5;
    const int h = w & 3, qh = w >> 2;

    #pragma unroll
    for (int i = 0; i < 4; i++) {
        int idx = t + i * 256;
        int row = idx >> 4, c = idx & 15;
        uint4 v = make_uint4(0, 0, 0, 0);
        if (row < nQ)
            v = *(const uint4*)(g_q + (size_t)(doff + q0 + row) * 128 + c * 8);
        *(uint4*)(qs + (row * 16 + (c ^ (row & 7))) * 8) = v;
    }

    const uint32_t baseQ = (uint32_t)__cvta_generic_to_shared(qs);
    const uint32_t baseK = (uint32_t)__cvta_generic_to_shared(ks);
    float acc[2][4][4] = {};
    float den[2][2] = {};
    const float sc2 = 0.25504167f;   // log2(e)/sqrt(32)

    const int nT = (ns + 31) >> 5;
    for (int tt = 0; tt < nT; tt++) {
        const int s0 = tt * 32;
        __syncthreads();
        #pragma unroll
        for (int i = 0; i < 4; i++) {
            int idx = t + i * 256;
            int row = idx >> 5, c = idx & 31;
            int gr = soff + s0 + row; if (gr >= TOTAL) gr = TOTAL - 1;
            uint4 v = *(const uint4*)(g_kv + (size_t)gr * 256 + c * 8);
            *(uint4*)(ks + (row * 32 + (c ^ (row & 7))) * 8) = v;
        }
        __syncthreads();

        // ---- S = Q K^T (per head, K=32) ----
        float S[2][4][4] = {};
        #pragma unroll
        for (int kk = 0; kk < 2; kk++) {
            uint32_t af[2][4];
            #pragma unroll
            for (int f = 0; f < 2; f++) {
                int row = qh * 32 + f * 16 + (lane & 15);
                int c8 = (h * 4 + kk * 2 + (lane >> 4)) ^ (row & 7);
                ldsm4(af[f][0], af[f][1], af[f][2], af[f][3],
                      baseQ + (row * 16 + c8) * 16);
            }
            uint32_t bk2[2][4];
            #pragma unroll
            for (int p = 0; p < 2; p++) {
                int row = p * 16 + (lane & 7) + ((lane >> 4) << 3);
                int c8 = (h * 4 + kk * 2 + ((lane >> 3) & 1)) ^ (row & 7);
                ldsm4(bk2[p][0], bk2[p][1], bk2[p][2], bk2[p][3],
                      baseK + (row * 32 + c8) * 16);
            }
            #pragma unroll
            for (int f = 0; f < 2; f++)
                #pragma unroll
                for (int n = 0; n < 4; n++)
                    mma_bf16(S[f][n], af[f], &bk2[n >> 1][(n & 1) * 2]);
        }

        // ---- exp + mask + den, pack P into A fragments ----
        uint32_t Ap[2][2][4];
        #pragma unroll
        for (int f = 0; f < 2; f++) {
            float d0 = 0.f, d1 = 0.f;
            #pragma unroll
            for (int n = 0; n < 4; n++) {
                int cb = s0 + n * 8 + (lane & 3) * 2;
                float e0 = ex2(S[f][n][0] * sc2); if (cb >= ns) e0 = 0.f;
                float e1 = ex2(S[f][n][1] * sc2); if (cb + 1 >= ns) e1 = 0.f;
                float e2 = ex2(S[f][n][2] * sc2); if (cb >= ns) e2 = 0.f;
                float e3 = ex2(S[f][n][3] * sc2); if (cb + 1 >= ns) e3 = 0.f;
                d0 += e0 + e1; d1 += e2 + e3;
                Ap[f][n >> 1][(n & 1) * 2]     = pk(e0, e1);
                Ap[f][n >> 1][(n & 1) * 2 + 1] = pk(e2, e3);
            }
            den[f][0] += d0; den[f][1] += d1;
        }

        // ---- O += P V (V B-frags via ldmatrix.trans) ----
        #pragma unroll
        for (int kk = 0; kk < 2; kk++) {
            uint32_t bv[2][4];
            #pragma unroll
            for (int p = 0; p < 2; p++) {
                int row = kk * 16 + (lane & 15);
                int c8 = (16 + h * 4 + p * 2 + (lane >> 4)) ^ (row & 7);
                ldsm4t(bv[p][0], bv[p][1], bv[p][2], bv[p][3],
                       baseK + (row * 32 + c8) * 16);
            }
            #pragma unroll
            for (int f = 0; f < 2; f++)
                #pragma unroll
                for (int n = 0; n < 4; n++)
                    mma_bf16(acc[f][n], Ap[f][kk], &bv[n >> 1][(n & 1) * 2]);
        }
    }

    #pragma unroll
    for (int f = 0; f < 2; f++)
        #pragma unroll
        for (int u = 0; u < 2; u++) {
            float v = den[f][u];
            v += __shfl_xor_sync(0xffffffffu, v, 1);
            v += __shfl_xor_sync(0xffffffffu, v, 2);
            den[f][u] = 1.f / v;
        }

    #pragma unroll
    for (int f = 0; f < 2; f++)
        #pragma unroll
        for (int n = 0; n < 4; n++)
            #pragma unroll
            for (int half = 0; half < 2; half++) {
                int rl = qh * 32 + f * 16 + (lane >> 2) + half * 8;
                if (rl < nQ) {
                    float inv = den[f][half];
                    __nv_bfloat162 o = __floats2bfloat162_rn(
                        acc[f][n][half * 2] * inv, acc[f][n][half * 2 + 1] * inv);
                    *(__nv_bfloat162*)(g_msg + (size_t)(doff + q0 + rl) * 128 +
                                       h * 32 + n * 8 + (lane & 3) * 2) = o;
                }
            }
}

// ------------------------------- launcher ----------------------------------
extern "C" void kernel_launch(void* const* d_in, const int* in_sizes, int n_in,
                              void* d_out, int out_size)
{
    const float* src_h = (const float*)d_in[0];
    const float* dst_h = (const float*)d_in[1];
    const void*  snv   = d_in[2];
    const void*  dnv   = d_in[3];
    const float* Wq = (const float*)d_in[4];  const float* bq = (const float*)d_in[5];
    const float* Wk = (const float*)d_in[6];  const float* bk = (const float*)d_in[7];
    const float* Wv = (const float*)d_in[8];  const float* bv = (const float*)d_in[9];
    const float* Wm = (const float*)d_in[10]; const float* bm = (const float*)d_in[11];
    const float* W1 = (const float*)d_in[12]; const float* b1 = (const float*)d_in[13];
    const float* g1 = (const float*)d_in[14]; const float* be1 = (const float*)d_in[15];
    const float* rm1 = (const float*)d_in[16]; const float* rv1 = (const float*)d_in[17];
    const float* W2 = (const float*)d_in[18]; const float* b2 = (const float*)d_in[19];
    const float* g2 = (const float*)d_in[20]; const float* be2 = (const float*)d_in[21];
    const float* rm2 = (const float*)d_in[22]; const float* rv2 = (const float*)d_in[23];
    float* out = (float*)d_out;

    __nv_bfloat16 *p_csrc, *p_cdst, *p_kv, *p_q, *p_msg, *p_x1;
    __nv_bfloat16 *p_Wkv, *p_Wq, *p_W1a, *p_W1bp, *p_W2b;
    float *p_y1a, *p_bkvp, *p_bqp, *p_b1p, *p_s1, *p_t1, *p_s2, *p_t2;
    cudaGetSymbolAddress((void**)&p_csrc, g_csrc);
    cudaGetSymbolAddress((void**)&p_cdst, g_cdst);
    cudaGetSymbolAddress((void**)&p_kv, g_kv);
    cudaGetSymbolAddress((void**)&p_q, g_q);
    cudaGetSymbolAddress((void**)&p_y1a, g_y1a);
    cudaGetSymbolAddress((void**)&p_msg, g_msg);
    cudaGetSymbolAddress((void**)&p_x1, g_x1);
    cudaGetSymbolAddress((void**)&p_Wkv, g_Wkv);
    cudaGetSymbolAddress((void**)&p_Wq, g_Wq);
    cudaGetSymbolAddress((void**)&p_W1a, g_W1a);
    cudaGetSymbolAddress((void**)&p_W1bp, g_W1bp);
    cudaGetSymbolAddress((void**)&p_W2b, g_W2b);
    cudaGetSymbolAddress((void**)&p_bkvp, g_bkvp);
    cudaGetSymbolAddress((void**)&p_bqp, g_bqp);
    cudaGetSymbolAddress((void**)&p_b1p, g_b1p);
    cudaGetSymbolAddress((void**)&p_s1, g_s1);
    cudaGetSymbolAddress((void**)&p_t1, g_t1);
    cudaGetSymbolAddress((void**)&p_s2, g_s2);
    cudaGetSymbolAddress((void**)&p_t2, g_t2);

    k_setup<<<1, 256>>>(snv, dnv, bq, bk, bv, bm, b1, g1, be1, rm1, rv1,
                        g2, be2, rm2, rv2, W1);
    k_convert<<<TOTAL * 256 / 8 / 256, 256>>>(src_h, dst_h);
    k_prep<<<256, 256>>>(Wk, Wv, Wq, W1, W2);
    k_w1bp<<<dim3(32, 4), 256>>>(W1, Wm);

    // G1: kv = src @ [Wk;Wv]'.T    (bf16 out, head-major)
    k_gemm<0, true><<<dim3(192, 4), 256>>>(p_csrc, 256, p_Wkv, p_bkvp,
                                           p_kv, 256, nullptr, 0, nullptr, nullptr);
    // G2a: q = dst @ Wq'.T         (bf16 out, head-major)
    k_gemm<0, true><<<dim3(192, 2), 256>>>(p_cdst, 256, p_Wq, p_bqp,
                                           p_q, 128, nullptr, 0, nullptr, nullptr);
    // G2b: y1a = dst @ W1a.T + b1' (fp32 out)
    k_gemm<0, false><<<dim3(192, 4), 256>>>(p_cdst, 256, p_W1a, p_b1p,
                                            p_y1a, 256, nullptr, 0, nullptr, nullptr);
    // A: msg = attention(q, k, v)  (bf16 out, head-major)
    k_attn<<<dim3(8, NSEG), 256>>>();
    // G3: x1 = relu((msg @ W1bp'.T + y1a) * s1 + t1)  (bf16 out)
    k_gemm<1, true><<<dim3(192, 4), 256>>>(p_msg, 128, p_W1bp, nullptr,
                                           p_x1, 256, p_y1a, 256, p_s1, p_t1);
    // G4: out = (x1 @ W2.T + b2) * s2 + t2 + dst_h    (fp32 out)
    k_gemm<2, false><<<dim3(192, 4), 256>>>(p_x1, 256, p_W2b, b2,
                                            out, 256, dst_h, 256, p_s2, p_t2);
}

// round 12
// speedup vs baseline: 1.0721x; 1.0538x over previous
#include <cuda_runtime.h>
#include <cuda_bf16.h>
#include <cstdint>

#define TOTAL 24576
#define NSEG  64

// ------------------------- device scratch (static) -------------------------
__device__ __nv_bfloat16 g_csrc[TOTAL * 256];
__device__ __nv_bfloat16 g_cdst[TOTAL * 256];
__device__ __nv_bfloat16 g_kv  [TOTAL * 256];   // head-major k|v, bf16
__device__ __nv_bfloat16 g_q   [TOTAL * 128];   // head-major q, bf16
__device__ float         g_y1a [TOTAL * 256];   // dst_h @ W1a.T + b1'
__device__ __nv_bfloat16 g_msg [TOTAL * 128];   // head-major attention out
__device__ __nv_bfloat16 g_x1  [TOTAL * 256];
__device__ __nv_bfloat16 g_Wkv [256 * 256];
__device__ __nv_bfloat16 g_Wq  [128 * 256];
__device__ __nv_bfloat16 g_W1a [256 * 256];
__device__ __nv_bfloat16 g_W1bb[256 * 128];     // bf16 W1b (A of W1bp GEMM)
__device__ __nv_bfloat16 g_WmT [128 * 128];     // bf16 Wm^T, head-major rows
__device__ __nv_bfloat16 g_W1bp[256 * 128];
__device__ __nv_bfloat16 g_W2b [256 * 256];
__device__ float g_bkvp[256], g_bqp[128], g_b1p[256];
__device__ float g_zero[128];                   // stays 0 (.bss)
__device__ float g_s1[256], g_t1[256], g_s2[256], g_t2[256];
__device__ int g_soff[NSEG + 1], g_doff[NSEG + 1], g_scnt[NSEG], g_dcnt[NSEG];

__device__ __forceinline__ int permc(int n) { return (n & 31) * 4 + (n >> 5); }

// ------------------------------ PTX helpers --------------------------------
__device__ __forceinline__ void ldsm4(uint32_t& r0, uint32_t& r1, uint32_t& r2,
                                      uint32_t& r3, uint32_t a) {
    asm volatile("ldmatrix.sync.aligned.m8n8.x4.shared.b16 {%0,%1,%2,%3}, [%4];"
                 : "=r"(r0), "=r"(r1), "=r"(r2), "=r"(r3) : "r"(a));
}
__device__ __forceinline__ void ldsm4t(uint32_t& r0, uint32_t& r1, uint32_t& r2,
                                       uint32_t& r3, uint32_t a) {
    asm volatile("ldmatrix.sync.aligned.m8n8.x4.trans.shared.b16 {%0,%1,%2,%3}, [%4];"
                 : "=r"(r0), "=r"(r1), "=r"(r2), "=r"(r3) : "r"(a));
}
__device__ __forceinline__ void mma_bf16(float c[4], const uint32_t a[4],
                                         const uint32_t b[2]) {
    asm volatile(
        "mma.sync.aligned.m16n8k16.row.col.f32.bf16.bf16.f32 "
        "{%0,%1,%2,%3},{%4,%5,%6,%7},{%8,%9},{%0,%1,%2,%3};"
        : "+f"(c[0]), "+f"(c[1]), "+f"(c[2]), "+f"(c[3])
        : "r"(a[0]), "r"(a[1]), "r"(a[2]), "r"(a[3]), "r"(b[0]), "r"(b[1]));
}
__device__ __forceinline__ float ex2(float x) {
    float r; asm("ex2.approx.f32 %0, %1;" : "=f"(r) : "f"(x)); return r;
}
__device__ __forceinline__ uint32_t pk(float a, float b) {
    __nv_bfloat162 v = __floats2bfloat162_rn(a, b);
    return *reinterpret_cast<uint32_t*>(&v);
}
__device__ __forceinline__ void cpa16(uint32_t s, const void* g) {
    asm volatile("cp.async.cg.shared.global [%0], [%1], 16;" :: "r"(s), "l"(g));
}
__device__ __forceinline__ void cpa_commit() {
    asm volatile("cp.async.commit_group;" ::: "memory");
}
template<int N>
__device__ __forceinline__ void cpa_wait() {
    asm volatile("cp.async.wait_group %0;" :: "n"(N) : "memory");
}

// ------------------------------- K0: setup ---------------------------------
__device__ __forceinline__ int read_count(const void* p, int i, bool is64) {
    if (is64) return (int)((const long long*)p)[i];
    return ((const int*)p)[i];
}

__global__ void k_setup(const void* snv, const void* dnv,
                        const float* __restrict__ bq, const float* __restrict__ bk,
                        const float* __restrict__ bv, const float* __restrict__ bm,
                        const float* __restrict__ b1,
                        const float* __restrict__ g1, const float* __restrict__ be1,
                        const float* __restrict__ rm1, const float* __restrict__ rv1,
                        const float* __restrict__ g2, const float* __restrict__ be2,
                        const float* __restrict__ rm2, const float* __restrict__ rv2,
                        const float* __restrict__ W1)
{
    int t = threadIdx.x;
    bool s64 = (((const int*)snv)[1] == 0);
    bool d64 = (((const int*)dnv)[1] == 0);
    __shared__ int sc[NSEG], dc[NSEG];
    if (t < NSEG) {
        sc[t] = read_count(snv, t, s64);
        dc[t] = read_count(dnv, t, d64);
    }
    __syncthreads();
    if (t == 0) {
        int ss = 0, dd = 0;
        for (int i = 0; i < NSEG; i++) {
            g_soff[i] = ss; g_doff[i] = dd;
            g_scnt[i] = sc[i]; g_dcnt[i] = dc[i];
            ss += sc[i]; dd += dc[i];
        }
        g_soff[NSEG] = ss; g_doff[NSEG] = dd;
    }
    {
        float s1v = g1[t] * rsqrtf(rv1[t] + 1e-5f);
        g_s1[t] = s1v; g_t1[t] = be1[t] - rm1[t] * s1v;
        float s2v = g2[t] * rsqrtf(rv2[t] + 1e-5f);
        g_s2[t] = s2v; g_t2[t] = be2[t] - rm2[t] * s2v;
    }
    if (t < 128) g_bqp[t] = bq[permc(t)];
    g_bkvp[t] = (t < 128) ? bk[permc(t)] : bv[permc(t - 128)];
    {   // b1' = b1 + W1b @ bm
        float acc = b1[t];
        const float* wrow = W1 + t * 384 + 256;
        #pragma unroll 8
        for (int j = 0; j < 128; j++) acc += wrow[j] * bm[j];
        g_b1p[t] = acc;
    }
}

// ---------------------- fp32 -> bf16 activation convert --------------------
__global__ void k_convert(const float* __restrict__ s, const float* __restrict__ d)
{
    int i = blockIdx.x * blockDim.x + threadIdx.x;   // over TOTAL*256/8
    const float4* s4 = (const float4*)s;
    const float4* d4 = (const float4*)d;
    float4 a = s4[2 * i], b = s4[2 * i + 1];
    uint4 o;
    o.x = pk(a.x, a.y); o.y = pk(a.z, a.w); o.z = pk(b.x, b.y); o.w = pk(b.z, b.w);
    ((uint4*)g_csrc)[i] = o;
    a = d4[2 * i]; b = d4[2 * i + 1];
    o.x = pk(a.x, a.y); o.y = pk(a.z, a.w); o.z = pk(b.x, b.y); o.w = pk(b.z, b.w);
    ((uint4*)g_cdst)[i] = o;
}

// ------------------------ weight conversion + permute ----------------------
__global__ void k_prep(const float* __restrict__ Wk, const float* __restrict__ Wv,
                       const float* __restrict__ Wq, const float* __restrict__ W1,
                       const float* __restrict__ W2, const float* __restrict__ Wm)
{
    int i = blockIdx.x * blockDim.x + threadIdx.x;   // 65536 threads
    {
        int n = i >> 8, k = i & 255;
        float v = (n < 128) ? Wk[permc(n) * 256 + k] : Wv[permc(n - 128) * 256 + k];
        g_Wkv[i] = __float2bfloat16(v);
    }
    if (i < 128 * 256) {
        int n = i >> 8, k = i & 255;
        g_Wq[i] = __float2bfloat16(Wq[permc(n) * 256 + k]);
    }
    {
        int n = i >> 8, k = i & 255;
        g_W1a[i] = __float2bfloat16(W1[n * 384 + k]);
    }
    g_W2b[i] = __float2bfloat16(W2[i]);
    // W1b -> bf16 (A operand of the W1bp GEMM)
    if (i < 256 * 128) {
        int n = i >> 7, k = i & 127;
        g_W1bb[i] = __float2bfloat16(W1[n * 384 + 256 + k]);
    }
    // Wm^T with head-major column permute folded into rows:
    // g_WmT[co][j] = Wm[j][cp], co = head-major position of cp
    if (i < 128 * 128) {
        int j = i >> 7, cp = i & 127;                // coalesced Wm read
        int co = (cp & 3) * 32 + (cp >> 2);
        g_WmT[co * 128 + j] = __float2bfloat16(Wm[i]);
    }
}

// ------------------------------ bf16 MMA GEMM ------------------------------
// C[M,N] = A[M,K](bf16) @ W[N,K](bf16)^T + epilogue. 128x64 block, BK=32,
// 256 thr = 8 warps (4m x 2n), warp tile 32x32 (2x4 m16n8k16 frags).
// 3-stage cp.async pipeline: one __syncthreads per k-iter, 2 stages in flight.
// MODE 0: acc + bias     MODE 1: relu((acc+aux)*s+t)   MODE 2: (acc+bias)*s+t+aux
template<int MODE, bool OBF>
__global__ __launch_bounds__(256) void k_gemm(
    const __nv_bfloat16* __restrict__ A, int K,
    const __nv_bfloat16* __restrict__ W,
    const float* __restrict__ bias,
    void* __restrict__ Cv, int N,
    const float* __restrict__ aux, int auxLd,
    const float* __restrict__ sbn, const float* __restrict__ tbn)
{
    constexpr int ST = 3;
    __shared__ __align__(16) __nv_bfloat16 As[ST][128 * 32];
    __shared__ __align__(16) __nv_bfloat16 Bs[ST][64 * 32];
    const int t = threadIdx.x, lane = t & 31, w = t >> 5;
    const int mw = w >> 1, nw = w & 1;
    const int m0 = blockIdx.x * 128, n0 = blockIdx.y * 64;

    const int rA = t >> 2, kc = t & 3;
    const int swz = kc ^ ((rA >> 1) & 3);
    const __nv_bfloat16* Ag0 = A + (size_t)(m0 + rA) * K + kc * 8;
    const __nv_bfloat16* Ag1 = Ag0 + (size_t)64 * K;
    const __nv_bfloat16* Wg  = W + (size_t)(n0 + rA) * K + kc * 8;
    const int oA0 = (rA * 4 + swz) * 8;              // element offsets in a stage
    const int oA1 = ((rA + 64) * 4 + swz) * 8;
    const int oB  = (rA * 4 + swz) * 8;
    const uint32_t baseA = (uint32_t)__cvta_generic_to_shared(As);
    const uint32_t baseB = (uint32_t)__cvta_generic_to_shared(Bs);

    const int nIter = K >> 5;

    // prologue: fill stages 0..ST-2
    #pragma unroll
    for (int s = 0; s < ST - 1; s++) {
        if (s < nIter) {
            cpa16(baseA + (s * 128 * 32 + oA0) * 2, Ag0 + s * 32);
            cpa16(baseA + (s * 128 * 32 + oA1) * 2, Ag1 + s * 32);
            cpa16(baseB + (s * 64 * 32 + oB) * 2,  Wg  + s * 32);
        }
        cpa_commit();
    }

    float acc[2][4][4] = {};
    int stage = 0;
    for (int i = 0; i < nIter; i++) {
        cpa_wait<ST - 2>();          // stage i resident
        __syncthreads();             // all writers of stage i done; all readers of
                                     // stage (i+2)%ST (read at iter i-1) passed
        {
            const int nx = i + ST - 1;
            if (nx < nIter) {
                const int sb = (stage + ST - 1) % ST;
                cpa16(baseA + (sb * 128 * 32 + oA0) * 2, Ag0 + nx * 32);
                cpa16(baseA + (sb * 128 * 32 + oA1) * 2, Ag1 + nx * 32);
                cpa16(baseB + (sb * 64 * 32 + oB) * 2,  Wg  + nx * 32);
            }
            cpa_commit();
        }
        const uint32_t bA = baseA + stage * (128 * 32 * 2);
        const uint32_t bB = baseB + stage * (64 * 32 * 2);
        #pragma unroll
        for (int kk = 0; kk < 2; kk++) {
            uint32_t af[2][4];
            #pragma unroll
            for (int f = 0; f < 2; f++) {
                int row = mw * 32 + f * 16 + (lane & 15);
                int c8 = (kk * 2 + (lane >> 4)) ^ ((row >> 1) & 3);
                ldsm4(af[f][0], af[f][1], af[f][2], af[f][3],
                      bA + (row * 4 + c8) * 16);
            }
            uint32_t bfr[2][4];
            #pragma unroll
            for (int p = 0; p < 2; p++) {
                int row = nw * 32 + p * 16 + (lane & 7) + ((lane >> 4) << 3);
                int c8 = (kk * 2 + ((lane >> 3) & 1)) ^ ((row >> 1) & 3);
                ldsm4(bfr[p][0], bfr[p][1], bfr[p][2], bfr[p][3],
                      bB + (row * 4 + c8) * 16);
            }
            #pragma unroll
            for (int f = 0; f < 2; f++)
                #pragma unroll
                for (int n = 0; n < 4; n++)
                    mma_bf16(acc[f][n], af[f], &bfr[n >> 1][(n & 1) * 2]);
        }
        stage = (stage + 1) % ST;
    }

    const int er = m0 + mw * 32 + (lane >> 2);
    const int ec = n0 + nw * 32 + (lane & 3) * 2;
    #pragma unroll
    for (int f = 0; f < 2; f++)
        #pragma unroll
        for (int n = 0; n < 4; n++)
            #pragma unroll
            for (int half = 0; half < 2; half++) {
                int r = er + f * 16 + half * 8;
                int c = ec + n * 8;
                float x0 = acc[f][n][half * 2], x1 = acc[f][n][half * 2 + 1];
                if (MODE == 0) {
                    x0 += bias[c]; x1 += bias[c + 1];
                } else if (MODE == 1) {
                    x0 += aux[(size_t)r * auxLd + c];
                    x1 += aux[(size_t)r * auxLd + c + 1];
                    x0 = fmaxf(x0 * sbn[c] + tbn[c], 0.f);
                    x1 = fmaxf(x1 * sbn[c + 1] + tbn[c + 1], 0.f);
                } else {
                    x0 = (x0 + bias[c]) * sbn[c] + tbn[c] + aux[(size_t)r * auxLd + c];
                    x1 = (x1 + bias[c + 1]) * sbn[c + 1] + tbn[c + 1] +
                         aux[(size_t)r * auxLd + c + 1];
                }
                if (OBF) {
                    __nv_bfloat162 h = __floats2bfloat162_rn(x0, x1);
                    *(__nv_bfloat162*)((__nv_bfloat16*)Cv + (size_t)r * N + c) = h;
                } else {
                    *(float2*)((float*)Cv + (size_t)r * N + c) = make_float2(x0, x1);
                }
            }
}

// ------------------------------- Attention ---------------------------------
// Block: 64 dst rows of one segment; 8 warps = 4 heads x 2 q-halves.
// Flash-style: S frags (fp32) -> ex2 -> in-register bf16 A frags -> PV mma,
// V B-frags via ldmatrix.trans straight from the row-major kv tile.
__global__ __launch_bounds__(256) void k_attn()
{
    __shared__ __align__(16) __nv_bfloat16 qs[64 * 128];
    __shared__ __align__(16) __nv_bfloat16 ks[32 * 256];
    const int b = blockIdx.y, q0 = blockIdx.x * 64;
    const int nd = g_dcnt[b];
    if (q0 >= nd) return;
    const int ns = g_scnt[b], soff = g_soff[b], doff = g_doff[b];
    const int nQ = min(64, nd - q0);
    const int t = threadIdx.x, lane = t & 31, w = t >> 5;
    const int h = w & 3, qh = w >> 2;

    #pragma unroll
    for (int i = 0; i < 4; i++) {
        int idx = t + i * 256;
        int row = idx >> 4, c = idx & 15;
        uint4 v = make_uint4(0, 0, 0, 0);
        if (row < nQ)
            v = *(const uint4*)(g_q + (size_t)(doff + q0 + row) * 128 + c * 8);
        *(uint4*)(qs + (row * 16 + (c ^ (row & 7))) * 8) = v;
    }

    const uint32_t baseQ = (uint32_t)__cvta_generic_to_shared(qs);
    const uint32_t baseK = (uint32_t)__cvta_generic_to_shared(ks);
    float acc[2][4][4] = {};
    float den[2][2] = {};
    const float sc2 = 0.25504167f;   // log2(e)/sqrt(32)

    const int nT = (ns + 31) >> 5;
    for (int tt = 0; tt < nT; tt++) {
        const int s0 = tt * 32;
        __syncthreads();
        #pragma unroll
        for (int i = 0; i < 4; i++) {
            int idx = t + i * 256;
            int row = idx >> 5, c = idx & 31;
            int gr = soff + s0 + row; if (gr >= TOTAL) gr = TOTAL - 1;
            uint4 v = *(const uint4*)(g_kv + (size_t)gr * 256 + c * 8);
            *(uint4*)(ks + (row * 32 + (c ^ (row & 7))) * 8) = v;
        }
        __syncthreads();

        // ---- S = Q K^T (per head, K=32) ----
        float S[2][4][4] = {};
        #pragma unroll
        for (int kk = 0; kk < 2; kk++) {
            uint32_t af[2][4];
            #pragma unroll
            for (int f = 0; f < 2; f++) {
                int row = qh * 32 + f * 16 + (lane & 15);
                int c8 = (h * 4 + kk * 2 + (lane >> 4)) ^ (row & 7);
                ldsm4(af[f][0], af[f][1], af[f][2], af[f][3],
                      baseQ + (row * 16 + c8) * 16);
            }
            uint32_t bk2[2][4];
            #pragma unroll
            for (int p = 0; p < 2; p++) {
                int row = p * 16 + (lane & 7) + ((lane >> 4) << 3);
                int c8 = (h * 4 + kk * 2 + ((lane >> 3) & 1)) ^ (row & 7);
                ldsm4(bk2[p][0], bk2[p][1], bk2[p][2], bk2[p][3],
                      baseK + (row * 32 + c8) * 16);
            }
            #pragma unroll
            for (int f = 0; f < 2; f++)
                #pragma unroll
                for (int n = 0; n < 4; n++)
                    mma_bf16(S[f][n], af[f], &bk2[n >> 1][(n & 1) * 2]);
        }

        // ---- exp + mask + den, pack P into A fragments ----
        uint32_t Ap[2][2][4];
        #pragma unroll
        for (int f = 0; f < 2; f++) {
            float d0 = 0.f, d1 = 0.f;
            #pragma unroll
            for (int n = 0; n < 4; n++) {
                int cb = s0 + n * 8 + (lane & 3) * 2;
                float e0 = ex2(S[f][n][0] * sc2); if (cb >= ns) e0 = 0.f;
                float e1 = ex2(S[f][n][1] * sc2); if (cb + 1 >= ns) e1 = 0.f;
                float e2 = ex2(S[f][n][2] * sc2); if (cb >= ns) e2 = 0.f;
                float e3 = ex2(S[f][n][3] * sc2); if (cb + 1 >= ns) e3 = 0.f;
                d0 += e0 + e1; d1 += e2 + e3;
                Ap[f][n >> 1][(n & 1) * 2]     = pk(e0, e1);
                Ap[f][n >> 1][(n & 1) * 2 + 1] = pk(e2, e3);
            }
            den[f][0] += d0; den[f][1] += d1;
        }

        // ---- O += P V (V B-frags via ldmatrix.trans) ----
        #pragma unroll
        for (int kk = 0; kk < 2; kk++) {
            uint32_t bv[2][4];
            #pragma unroll
            for (int p = 0; p < 2; p++) {
                int row = kk * 16 + (lane & 15);
                int c8 = (16 + h * 4 + p * 2 + (lane >> 4)) ^ (row & 7);
                ldsm4t(bv[p][0], bv[p][1], bv[p][2], bv[p][3],
                       baseK + (row * 32 + c8) * 16);
            }
            #pragma unroll
            for (int f = 0; f < 2; f++)
                #pragma unroll
                for (int n = 0; n < 4; n++)
                    mma_bf16(acc[f][n], Ap[f][kk], &bv[n >> 1][(n & 1) * 2]);
        }
    }

    #pragma unroll
    for (int f = 0; f < 2; f++)
        #pragma unroll
        for (int u = 0; u < 2; u++) {
            float v = den[f][u];
            v += __shfl_xor_sync(0xffffffffu, v, 1);
            v += __shfl_xor_sync(0xffffffffu, v, 2);
            den[f][u] = 1.f / v;
        }

    #pragma unroll
    for (int f = 0; f < 2; f++)
        #pragma unroll
        for (int n = 0; n < 4; n++)
            #pragma unroll
            for (int half = 0; half < 2; half++) {
                int rl = qh * 32 + f * 16 + (lane >> 2) + half * 8;
                if (rl < nQ) {
                    float inv = den[f][half];
                    __nv_bfloat162 o = __floats2bfloat162_rn(
                        acc[f][n][half * 2] * inv, acc[f][n][half * 2 + 1] * inv);
                    *(__nv_bfloat162*)(g_msg + (size_t)(doff + q0 + rl) * 128 +
                                       h * 32 + n * 8 + (lane & 3) * 2) = o;
                }
            }
}

// ------------------------------- launcher ----------------------------------
extern "C" void kernel_launch(void* const* d_in, const int* in_sizes, int n_in,
                              void* d_out, int out_size)
{
    const float* src_h = (const float*)d_in[0];
    const float* dst_h = (const float*)d_in[1];
    const void*  snv   = d_in[2];
    const void*  dnv   = d_in[3];
    const float* Wq = (const float*)d_in[4];  const float* bq = (const float*)d_in[5];
    const float* Wk = (const float*)d_in[6];  const float* bk = (const float*)d_in[7];
    const float* Wv = (const float*)d_in[8];  const float* bv = (const float*)d_in[9];
    const float* Wm = (const float*)d_in[10]; const float* bm = (const float*)d_in[11];
    const float* W1 = (const float*)d_in[12]; const float* b1 = (const float*)d_in[13];
    const float* g1 = (const float*)d_in[14]; const float* be1 = (const float*)d_in[15];
    const float* rm1 = (const float*)d_in[16]; const float* rv1 = (const float*)d_in[17];
    const float* W2 = (const float*)d_in[18]; const float* b2 = (const float*)d_in[19];
    const float* g2 = (const float*)d_in[20]; const float* be2 = (const float*)d_in[21];
    const float* rm2 = (const float*)d_in[22]; const float* rv2 = (const float*)d_in[23];
    float* out = (float*)d_out;

    __nv_bfloat16 *p_csrc, *p_cdst, *p_kv, *p_q, *p_msg, *p_x1;
    __nv_bfloat16 *p_Wkv, *p_Wq, *p_W1a, *p_W1bb, *p_WmT, *p_W1bp, *p_W2b;
    float *p_y1a, *p_bkvp, *p_bqp, *p_b1p, *p_zero, *p_s1, *p_t1, *p_s2, *p_t2;
    cudaGetSymbolAddress((void**)&p_csrc, g_csrc);
    cudaGetSymbolAddress((void**)&p_cdst, g_cdst);
    cudaGetSymbolAddress((void**)&p_kv, g_kv);
    cudaGetSymbolAddress((void**)&p_q, g_q);
    cudaGetSymbolAddress((void**)&p_y1a, g_y1a);
    cudaGetSymbolAddress((void**)&p_msg, g_msg);
    cudaGetSymbolAddress((void**)&p_x1, g_x1);
    cudaGetSymbolAddress((void**)&p_Wkv, g_Wkv);
    cudaGetSymbolAddress((void**)&p_Wq, g_Wq);
    cudaGetSymbolAddress((void**)&p_W1a, g_W1a);
    cudaGetSymbolAddress((void**)&p_W1bb, g_W1bb);
    cudaGetSymbolAddress((void**)&p_WmT, g_WmT);
    cudaGetSymbolAddress((void**)&p_W1bp, g_W1bp);
    cudaGetSymbolAddress((void**)&p_W2b, g_W2b);
    cudaGetSymbolAddress((void**)&p_bkvp, g_bkvp);
    cudaGetSymbolAddress((void**)&p_bqp, g_bqp);
    cudaGetSymbolAddress((void**)&p_b1p, g_b1p);
    cudaGetSymbolAddress((void**)&p_zero, g_zero);
    cudaGetSymbolAddress((void**)&p_s1, g_s1);
    cudaGetSymbolAddress((void**)&p_t1, g_t1);
    cudaGetSymbolAddress((void**)&p_s2, g_s2);
    cudaGetSymbolAddress((void**)&p_t2, g_t2);

    k_setup<<<1, 256>>>(snv, dnv, bq, bk, bv, bm, b1, g1, be1, rm1, rv1,
                        g2, be2, rm2, rv2, W1);
    k_convert<<<TOTAL * 256 / 8 / 256, 256>>>(src_h, dst_h);
    k_prep<<<256, 256>>>(Wk, Wv, Wq, W1, W2, Wm);

    // W1bp = W1b @ Wm  (tensor-core GEMM, M=256 N=128 K=128, zero bias)
    k_gemm<0, true><<<dim3(2, 2), 256>>>(p_W1bb, 128, p_WmT, p_zero,
                                         p_W1bp, 128, nullptr, 0, nullptr, nullptr);

    // G1: kv = src @ [Wk;Wv]'.T    (bf16 out, head-major)
    k_gemm<0, true><<<dim3(192, 4), 256>>>(p_csrc, 256, p_Wkv, p_bkvp,
                                           p_kv, 256, nullptr, 0, nullptr, nullptr);
    // G2a: q = dst @ Wq'.T         (bf16 out, head-major)
    k_gemm<0, true><<<dim3(192, 2), 256>>>(p_cdst, 256, p_Wq, p_bqp,
                                           p_q, 128, nullptr, 0, nullptr, nullptr);
    // G2b: y1a = dst @ W1a.T + b1' (fp32 out)
    k_gemm<0, false><<<dim3(192, 4), 256>>>(p_cdst, 256, p_W1a, p_b1p,
                                            p_y1a, 256, nullptr, 0, nullptr, nullptr);
    // A: msg = attention(q, k, v)  (bf16 out, head-major)
    k_attn<<<dim3(8, NSEG), 256>>>();
    // G3: x1 = relu((msg @ W1bp'.T + y1a) * s1 + t1)  (bf16 out)
    k_gemm<1, true><<<dim3(192, 4), 256>>>(p_msg, 128, p_W1bp, nullptr,
                                           p_x1, 256, p_y1a, 256, p_s1, p_t1);
    // G4: out = (x1 @ W2.T + b2) * s2 + t2 + dst_h    (fp32 out)
    k_gemm<2, false><<<dim3(192, 4), 256>>>(p_x1, 256, p_W2b, b2,
                                            out, 256, dst_h, 256, p_s2, p_t2);
}

// round 15
// speedup vs baseline: 1.0960x; 1.0223x over previous
#include <cuda_runtime.h>
#include <cuda_bf16.h>
#include <cstdint>

#define TOTAL 24576
#define NSEG  64

// ------------------------- device scratch (static) -------------------------
__device__ __nv_bfloat16 g_csrc[TOTAL * 256];
__device__ __nv_bfloat16 g_cdst[TOTAL * 256];
__device__ __nv_bfloat16 g_kv  [TOTAL * 256];   // head-major k|v, bf16
__device__ __nv_bfloat16 g_q   [TOTAL * 128];   // head-major q, bf16
__device__ float         g_y1a [TOTAL * 256];   // dst_h @ W1a.T + b1'
__device__ __nv_bfloat16 g_msg [TOTAL * 128];   // head-major attention out
__device__ __nv_bfloat16 g_x1  [TOTAL * 256];
__device__ __nv_bfloat16 g_Wkv [256 * 256];
__device__ __nv_bfloat16 g_Wqy [384 * 256];     // [Wq(perm); W1a]
__device__ __nv_bfloat16 g_W1bb[256 * 128];     // bf16 W1b (A of W1bp GEMM)
__device__ __nv_bfloat16 g_WmT [128 * 128];     // bf16 Wm^T, head-major rows
__device__ __nv_bfloat16 g_W1bp[256 * 128];
__device__ __nv_bfloat16 g_W2b [256 * 256];
__device__ float g_bkvp[256], g_bqy[384];
__device__ float g_zero[128];                   // stays 0 (.bss)
__device__ float g_s1[256], g_t1[256], g_s2[256], g_t2[256];
__device__ int g_soff[NSEG + 1], g_doff[NSEG + 1], g_scnt[NSEG], g_dcnt[NSEG];

__device__ __forceinline__ int permc(int n) { return (n & 31) * 4 + (n >> 5); }

// ------------------------------ PTX helpers --------------------------------
__device__ __forceinline__ void ldsm4(uint32_t& r0, uint32_t& r1, uint32_t& r2,
                                      uint32_t& r3, uint32_t a) {
    asm volatile("ldmatrix.sync.aligned.m8n8.x4.shared.b16 {%0,%1,%2,%3}, [%4];"
                 : "=r"(r0), "=r"(r1), "=r"(r2), "=r"(r3) : "r"(a));
}
__device__ __forceinline__ void ldsm4t(uint32_t& r0, uint32_t& r1, uint32_t& r2,
                                       uint32_t& r3, uint32_t a) {
    asm volatile("ldmatrix.sync.aligned.m8n8.x4.trans.shared.b16 {%0,%1,%2,%3}, [%4];"
                 : "=r"(r0), "=r"(r1), "=r"(r2), "=r"(r3) : "r"(a));
}
__device__ __forceinline__ void mma_bf16(float c[4], const uint32_t a[4],
                                         const uint32_t b[2]) {
    asm volatile(
        "mma.sync.aligned.m16n8k16.row.col.f32.bf16.bf16.f32 "
        "{%0,%1,%2,%3},{%4,%5,%6,%7},{%8,%9},{%0,%1,%2,%3};"
        : "+f"(c[0]), "+f"(c[1]), "+f"(c[2]), "+f"(c[3])
        : "r"(a[0]), "r"(a[1]), "r"(a[2]), "r"(a[3]), "r"(b[0]), "r"(b[1]));
}
__device__ __forceinline__ float ex2(float x) {
    float r; asm("ex2.approx.f32 %0, %1;" : "=f"(r) : "f"(x)); return r;
}
__device__ __forceinline__ uint32_t pk(float a, float b) {
    __nv_bfloat162 v = __floats2bfloat162_rn(a, b);
    return *reinterpret_cast<uint32_t*>(&v);
}
__device__ __forceinline__ void cpa16(uint32_t s, const void* g) {
    asm volatile("cp.async.cg.shared.global [%0], [%1], 16;" :: "r"(s), "l"(g));
}
__device__ __forceinline__ void cpa_commit() {
    asm volatile("cp.async.commit_group;" ::: "memory");
}
template<int N>
__device__ __forceinline__ void cpa_wait() {
    asm volatile("cp.async.wait_group %0;" :: "n"(N) : "memory");
}

// ------------------------------- K0: setup ---------------------------------
__device__ __forceinline__ int read_count(const void* p, int i, bool is64) {
    if (is64) return (int)((const long long*)p)[i];
    return ((const int*)p)[i];
}

__global__ void k_setup(const void* snv, const void* dnv,
                        const float* __restrict__ bq, const float* __restrict__ bk,
                        const float* __restrict__ bv, const float* __restrict__ bm,
                        const float* __restrict__ b1,
                        const float* __restrict__ g1, const float* __restrict__ be1,
                        const float* __restrict__ rm1, const float* __restrict__ rv1,
                        const float* __restrict__ g2, const float* __restrict__ be2,
                        const float* __restrict__ rm2, const float* __restrict__ rv2,
                        const float* __restrict__ W1)
{
    int t = threadIdx.x;
    bool s64 = (((const int*)snv)[1] == 0);
    bool d64 = (((const int*)dnv)[1] == 0);
    __shared__ int sc[NSEG], dc[NSEG];
    if (t < NSEG) {
        sc[t] = read_count(snv, t, s64);
        dc[t] = read_count(dnv, t, d64);
    }
    __syncthreads();
    if (t == 0) {
        int ss = 0, dd = 0;
        for (int i = 0; i < NSEG; i++) {
            g_soff[i] = ss; g_doff[i] = dd;
            g_scnt[i] = sc[i]; g_dcnt[i] = dc[i];
            ss += sc[i]; dd += dc[i];
        }
        g_soff[NSEG] = ss; g_doff[NSEG] = dd;
    }
    {
        float s1v = g1[t] * rsqrtf(rv1[t] + 1e-5f);
        g_s1[t] = s1v; g_t1[t] = be1[t] - rm1[t] * s1v;
        float s2v = g2[t] * rsqrtf(rv2[t] + 1e-5f);
        g_s2[t] = s2v; g_t2[t] = be2[t] - rm2[t] * s2v;
    }
    if (t < 128) g_bqy[t] = bq[permc(t)];
    g_bkvp[t] = (t < 128) ? bk[permc(t)] : bv[permc(t - 128)];
    {   // b1' = b1 + W1b @ bm -> g_bqy[128 + t]
        float acc = b1[t];
        const float* wrow = W1 + t * 384 + 256;
        #pragma unroll 8
        for (int j = 0; j < 128; j++) acc += wrow[j] * bm[j];
        g_bqy[128 + t] = acc;
    }
}

// ---------------------- fp32 -> bf16 activation convert --------------------
__global__ void k_convert(const float* __restrict__ s, const float* __restrict__ d)
{
    int i = blockIdx.x * blockDim.x + threadIdx.x;   // over TOTAL*256/8
    const float4* s4 = (const float4*)s;
    const float4* d4 = (const float4*)d;
    float4 a = s4[2 * i], b = s4[2 * i + 1];
    uint4 o;
    o.x = pk(a.x, a.y); o.y = pk(a.z, a.w); o.z = pk(b.x, b.y); o.w = pk(b.z, b.w);
    ((uint4*)g_csrc)[i] = o;
    a = d4[2 * i]; b = d4[2 * i + 1];
    o.x = pk(a.x, a.y); o.y = pk(a.z, a.w); o.z = pk(b.x, b.y); o.w = pk(b.z, b.w);
    ((uint4*)g_cdst)[i] = o;
}

// ------------------------ weight conversion + permute ----------------------
__global__ void k_prep(const float* __restrict__ Wk, const float* __restrict__ Wv,
                       const float* __restrict__ Wq, const float* __restrict__ W1,
                       const float* __restrict__ W2, const float* __restrict__ Wm)
{
    int i = blockIdx.x * blockDim.x + threadIdx.x;   // 65536 threads
    {
        int n = i >> 8, k = i & 255;
        float v = (n < 128) ? Wk[permc(n) * 256 + k] : Wv[permc(n - 128) * 256 + k];
        g_Wkv[i] = __float2bfloat16(v);
    }
    // Wqy = [Wq(perm rows); W1a] : 384 x 256 (strided, 2 passes)
    #pragma unroll
    for (int pass = 0; pass < 2; pass++) {
        int j = i + pass * 65536;
        if (j < 384 * 256) {
            int n = j >> 8, k = j & 255;
            float v = (n < 128) ? Wq[permc(n) * 256 + k] : W1[(n - 128) * 384 + k];
            g_Wqy[j] = __float2bfloat16(v);
        }
    }
    g_W2b[i] = __float2bfloat16(W2[i]);
    // W1b -> bf16 (A operand of the W1bp GEMM)
    if (i < 256 * 128) {
        int n = i >> 7, k = i & 127;
        g_W1bb[i] = __float2bfloat16(W1[n * 384 + 256 + k]);
    }
    // Wm^T with head-major column permute folded into rows
    if (i < 128 * 128) {
        int j = i >> 7, cp = i & 127;
        int co = (cp & 3) * 32 + (cp >> 2);
        g_WmT[co * 128 + j] = __float2bfloat16(Wm[i]);
    }
}

// ------------------------------ bf16 MMA GEMM ------------------------------
// C[M,N] = A[M,K](bf16) @ W[N,K](bf16)^T + epilogue. 128x64 block, BK=32,
// 256 thr = 8 warps (4m x 2n), warp tile 32x32. 3-stage cp.async pipeline.
// MODE 0: acc + bias                MODE 1: relu((acc+aux)*s+t)
// MODE 2: (acc+bias)*s+t+aux       MODE 3: n0<128 -> bf16 Cv (ld 128),
//                                          n0>=128 -> fp32 C2 (ld 256, c-128)
template<int MODE, bool OBF>
__global__ __launch_bounds__(256) void k_gemm(
    const __nv_bfloat16* __restrict__ A, int K,
    const __nv_bfloat16* __restrict__ W,
    const float* __restrict__ bias,
    void* __restrict__ Cv, int N,
    const float* __restrict__ aux, int auxLd,
    const float* __restrict__ sbn, const float* __restrict__ tbn,
    float* __restrict__ C2 = nullptr)
{
    constexpr int ST = 3;
    __shared__ __align__(16) __nv_bfloat16 As[ST][128 * 32];
    __shared__ __align__(16) __nv_bfloat16 Bs[ST][64 * 32];
    const int t = threadIdx.x, lane = t & 31, w = t >> 5;
    const int mw = w >> 1, nw = w & 1;
    const int m0 = blockIdx.x * 128, n0 = blockIdx.y * 64;

    const int rA = t >> 2, kc = t & 3;
    const int swz = kc ^ ((rA >> 1) & 3);
    const __nv_bfloat16* Ag0 = A + (size_t)(m0 + rA) * K + kc * 8;
    const __nv_bfloat16* Ag1 = Ag0 + (size_t)64 * K;
    const __nv_bfloat16* Wg  = W + (size_t)(n0 + rA) * K + kc * 8;
    const int oA0 = (rA * 4 + swz) * 8;
    const int oA1 = ((rA + 64) * 4 + swz) * 8;
    const int oB  = (rA * 4 + swz) * 8;
    const uint32_t baseA = (uint32_t)__cvta_generic_to_shared(As);
    const uint32_t baseB = (uint32_t)__cvta_generic_to_shared(Bs);

    const int nIter = K >> 5;

    #pragma unroll
    for (int s = 0; s < ST - 1; s++) {
        if (s < nIter) {
            cpa16(baseA + (s * 128 * 32 + oA0) * 2, Ag0 + s * 32);
            cpa16(baseA + (s * 128 * 32 + oA1) * 2, Ag1 + s * 32);
            cpa16(baseB + (s * 64 * 32 + oB) * 2,  Wg  + s * 32);
        }
        cpa_commit();
    }

    float acc[2][4][4] = {};
    int stage = 0;
    for (int i = 0; i < nIter; i++) {
        cpa_wait<ST - 2>();
        __syncthreads();
        {
            const int nx = i + ST - 1;
            if (nx < nIter) {
                const int sb = (stage + ST - 1) % ST;
                cpa16(baseA + (sb * 128 * 32 + oA0) * 2, Ag0 + nx * 32);
                cpa16(baseA + (sb * 128 * 32 + oA1) * 2, Ag1 + nx * 32);
                cpa16(baseB + (sb * 64 * 32 + oB) * 2,  Wg  + nx * 32);
            }
            cpa_commit();
        }
        const uint32_t bA = baseA + stage * (128 * 32 * 2);
        const uint32_t bB = baseB + stage * (64 * 32 * 2);
        #pragma unroll
        for (int kk = 0; kk < 2; kk++) {
            uint32_t af[2][4];
            #pragma unroll
            for (int f = 0; f < 2; f++) {
                int row = mw * 32 + f * 16 + (lane & 15);
                int c8 = (kk * 2 + (lane >> 4)) ^ ((row >> 1) & 3);
                ldsm4(af[f][0], af[f][1], af[f][2], af[f][3],
                      bA + (row * 4 + c8) * 16);
            }
            uint32_t bfr[2][4];
            #pragma unroll
            for (int p = 0; p < 2; p++) {
                int row = nw * 32 + p * 16 + (lane & 7) + ((lane >> 4) << 3);
                int c8 = (kk * 2 + ((lane >> 3) & 1)) ^ ((row >> 1) & 3);
                ldsm4(bfr[p][0], bfr[p][1], bfr[p][2], bfr[p][3],
                      bB + (row * 4 + c8) * 16);
            }
            #pragma unroll
            for (int f = 0; f < 2; f++)
                #pragma unroll
                for (int n = 0; n < 4; n++)
                    mma_bf16(acc[f][n], af[f], &bfr[n >> 1][(n & 1) * 2]);
        }
        stage = (stage + 1) % ST;
    }

    const int er = m0 + mw * 32 + (lane >> 2);
    const int ec = n0 + nw * 32 + (lane & 3) * 2;
    #pragma unroll
    for (int f = 0; f < 2; f++)
        #pragma unroll
        for (int n = 0; n < 4; n++)
            #pragma unroll
            for (int half = 0; half < 2; half++) {
                int r = er + f * 16 + half * 8;
                int c = ec + n * 8;
                float x0 = acc[f][n][half * 2], x1 = acc[f][n][half * 2 + 1];
                if (MODE == 0) {
                    x0 += bias[c]; x1 += bias[c + 1];
                } else if (MODE == 1) {
                    x0 += aux[(size_t)r * auxLd + c];
                    x1 += aux[(size_t)r * auxLd + c + 1];
                    x0 = fmaxf(x0 * sbn[c] + tbn[c], 0.f);
                    x1 = fmaxf(x1 * sbn[c + 1] + tbn[c + 1], 0.f);
                } else if (MODE == 2) {
                    x0 = (x0 + bias[c]) * sbn[c] + tbn[c] + aux[(size_t)r * auxLd + c];
                    x1 = (x1 + bias[c + 1]) * sbn[c + 1] + tbn[c + 1] +
                         aux[(size_t)r * auxLd + c + 1];
                } else {                               // MODE 3: fused q | y1a
                    x0 += bias[c]; x1 += bias[c + 1];
                    if (n0 < 128) {
                        *(__nv_bfloat162*)((__nv_bfloat16*)Cv + (size_t)r * 128 + c) =
                            __floats2bfloat162_rn(x0, x1);
                    } else {
                        *(float2*)(C2 + (size_t)r * 256 + (c - 128)) =
                            make_float2(x0, x1);
                    }
                    continue;
                }
                if (OBF) {
                    __nv_bfloat162 h = __floats2bfloat162_rn(x0, x1);
                    *(__nv_bfloat162*)((__nv_bfloat16*)Cv + (size_t)r * N + c) = h;
                } else {
                    *(float2*)((float*)Cv + (size_t)r * N + c) = make_float2(x0, x1);
                }
            }
}

// ------------------------------- Attention ---------------------------------
// Block: 64 dst rows of one segment; 8 warps = 4 heads x 2 q-halves.
__global__ __launch_bounds__(256) void k_attn()
{
    __shared__ __align__(16) __nv_bfloat16 qs[64 * 128];
    __shared__ __align__(16) __nv_bfloat16 ks[32 * 256];
    const int b = blockIdx.y, q0 = blockIdx.x * 64;
    const int nd = g_dcnt[b];
    if (q0 >= nd) return;
    const int ns = g_scnt[b], soff = g_soff[b], doff = g_doff[b];
    const int nQ = min(64, nd - q0);
    const int t = threadIdx.x, lane = t & 31, w = t >> 5;
    const int h = w & 3, qh = w >> 2;

    #pragma unroll
    for (int i = 0; i < 4; i++) {
        int idx = t + i * 256;
        int row = idx >> 4, c = idx & 15;
        uint4 v = make_uint4(0, 0, 0, 0);
        if (row < nQ)
            v = *(const uint4*)(g_q + (size_t)(doff + q0 + row) * 128 + c * 8);
        *(uint4*)(qs + (row * 16 + (c ^ (row & 7))) * 8) = v;
    }

    const uint32_t baseQ = (uint32_t)__cvta_generic_to_shared(qs);
    const uint32_t baseK = (uint32_t)__cvta_generic_to_shared(ks);
    float acc[2][4][4] = {};
    float den[2][2] = {};
    const float sc2 = 0.25504167f;   // log2(e)/sqrt(32)

    const int nT = (ns + 31) >> 5;
    for (int tt = 0; tt < nT; tt++) {
        const int s0 = tt * 32;
        __syncthreads();
        #pragma unroll
        for (int i = 0; i < 4; i++) {
            int idx = t + i * 256;
            int row = idx >> 5, c = idx & 31;
            int gr = soff + s0 + row; if (gr >= TOTAL) gr = TOTAL - 1;
            uint4 v = *(const uint4*)(g_kv + (size_t)gr * 256 + c * 8);
            *(uint4*)(ks + (row * 32 + (c ^ (row & 7))) * 8) = v;
        }
        __syncthreads();

        float S[2][4][4] = {};
        #pragma unroll
        for (int kk = 0; kk < 2; kk++) {
            uint32_t af[2][4];
            #pragma unroll
            for (int f = 0; f < 2; f++) {
                int row = qh * 32 + f * 16 + (lane & 15);
                int c8 = (h * 4 + kk * 2 + (lane >> 4)) ^ (row & 7);
                ldsm4(af[f][0], af[f][1], af[f][2], af[f][3],
                      baseQ + (row * 16 + c8) * 16);
            }
            uint32_t bk2[2][4];
            #pragma unroll
            for (int p = 0; p < 2; p++) {
                int row = p * 16 + (lane & 7) + ((lane >> 4) << 3);
                int c8 = (h * 4 + kk * 2 + ((lane >> 3) & 1)) ^ (row & 7);
                ldsm4(bk2[p][0], bk2[p][1], bk2[p][2], bk2[p][3],
                      baseK + (row * 32 + c8) * 16);
            }
            #pragma unroll
            for (int f = 0; f < 2; f++)
                #pragma unroll
                for (int n = 0; n < 4; n++)
                    mma_bf16(S[f][n], af[f], &bk2[n >> 1][(n & 1) * 2]);
        }

        uint32_t Ap[2][2][4];
        #pragma unroll
        for (int f = 0; f < 2; f++) {
            float d0 = 0.f, d1 = 0.f;
            #pragma unroll
            for (int n = 0; n < 4; n++) {
                int cb = s0 + n * 8 + (lane & 3) * 2;
                float e0 = ex2(S[f][n][0] * sc2); if (cb >= ns) e0 = 0.f;
                float e1 = ex2(S[f][n][1] * sc2); if (cb + 1 >= ns) e1 = 0.f;
                float e2 = ex2(S[f][n][2] * sc2); if (cb >= ns) e2 = 0.f;
                float e3 = ex2(S[f][n][3] * sc2); if (cb + 1 >= ns) e3 = 0.f;
                d0 += e0 + e1; d1 += e2 + e3;
                Ap[f][n >> 1][(n & 1) * 2]     = pk(e0, e1);
                Ap[f][n >> 1][(n & 1) * 2 + 1] = pk(e2, e3);
            }
            den[f][0] += d0; den[f][1] += d1;
        }

        #pragma unroll
        for (int kk = 0; kk < 2; kk++) {
            uint32_t bv[2][4];
            #pragma unroll
            for (int p = 0; p < 2; p++) {
                int row = kk * 16 + (lane & 15);
                int c8 = (16 + h * 4 + p * 2 + (lane >> 4)) ^ (row & 7);
                ldsm4t(bv[p][0], bv[p][1], bv[p][2], bv[p][3],
                       baseK + (row * 32 + c8) * 16);
            }
            #pragma unroll
            for (int f = 0; f < 2; f++)
                #pragma unroll
                for (int n = 0; n < 4; n++)
                    mma_bf16(acc[f][n], Ap[f][kk], &bv[n >> 1][(n & 1) * 2]);
        }
    }

    #pragma unroll
    for (int f = 0; f < 2; f++)
        #pragma unroll
        for (int u = 0; u < 2; u++) {
            float v = den[f][u];
            v += __shfl_xor_sync(0xffffffffu, v, 1);
            v += __shfl_xor_sync(0xffffffffu, v, 2);
            den[f][u] = 1.f / v;
        }

    #pragma unroll
    for (int f = 0; f < 2; f++)
        #pragma unroll
        for (int n = 0; n < 4; n++)
            #pragma unroll
            for (int half = 0; half < 2; half++) {
                int rl = qh * 32 + f * 16 + (lane >> 2) + half * 8;
                if (rl < nQ) {
                    float inv = den[f][half];
                    __nv_bfloat162 o = __floats2bfloat162_rn(
                        acc[f][n][half * 2] * inv, acc[f][n][half * 2 + 1] * inv);
                    *(__nv_bfloat162*)(g_msg + (size_t)(doff + q0 + rl) * 128 +
                                       h * 32 + n * 8 + (lane & 3) * 2) = o;
                }
            }
}

// ------------------------------- launcher ----------------------------------
extern "C" void kernel_launch(void* const* d_in, const int* in_sizes, int n_in,
                              void* d_out, int out_size)
{
    const float* src_h = (const float*)d_in[0];
    const float* dst_h = (const float*)d_in[1];
    const void*  snv   = d_in[2];
    const void*  dnv   = d_in[3];
    const float* Wq = (const float*)d_in[4];  const float* bq = (const float*)d_in[5];
    const float* Wk = (const float*)d_in[6];  const float* bk = (const float*)d_in[7];
    const float* Wv = (const float*)d_in[8];  const float* bv = (const float*)d_in[9];
    const float* Wm = (const float*)d_in[10]; const float* bm = (const float*)d_in[11];
    const float* W1 = (const float*)d_in[12]; const float* b1 = (const float*)d_in[13];
    const float* g1 = (const float*)d_in[14]; const float* be1 = (const float*)d_in[15];
    const float* rm1 = (const float*)d_in[16]; const float* rv1 = (const float*)d_in[17];
    const float* W2 = (const float*)d_in[18]; const float* b2 = (const float*)d_in[19];
    const float* g2 = (const float*)d_in[20]; const float* be2 = (const float*)d_in[21];
    const float* rm2 = (const float*)d_in[22]; const float* rv2 = (const float*)d_in[23];
    float* out = (float*)d_out;

    __nv_bfloat16 *p_csrc, *p_cdst, *p_kv, *p_q, *p_msg, *p_x1;
    __nv_bfloat16 *p_Wkv, *p_Wqy, *p_W1bb, *p_WmT, *p_W1bp, *p_W2b;
    float *p_y1a, *p_bkvp, *p_bqy, *p_zero, *p_s1, *p_t1, *p_s2, *p_t2;
    cudaGetSymbolAddress((void**)&p_csrc, g_csrc);
    cudaGetSymbolAddress((void**)&p_cdst, g_cdst);
    cudaGetSymbolAddress((void**)&p_kv, g_kv);
    cudaGetSymbolAddress((void**)&p_q, g_q);
    cudaGetSymbolAddress((void**)&p_y1a, g_y1a);
    cudaGetSymbolAddress((void**)&p_msg, g_msg);
    cudaGetSymbolAddress((void**)&p_x1, g_x1);
    cudaGetSymbolAddress((void**)&p_Wkv, g_Wkv);
    cudaGetSymbolAddress((void**)&p_Wqy, g_Wqy);
    cudaGetSymbolAddress((void**)&p_W1bb, g_W1bb);
    cudaGetSymbolAddress((void**)&p_WmT, g_WmT);
    cudaGetSymbolAddress((void**)&p_W1bp, g_W1bp);
    cudaGetSymbolAddress((void**)&p_W2b, g_W2b);
    cudaGetSymbolAddress((void**)&p_bkvp, g_bkvp);
    cudaGetSymbolAddress((void**)&p_bqy, g_bqy);
    cudaGetSymbolAddress((void**)&p_zero, g_zero);
    cudaGetSymbolAddress((void**)&p_s1, g_s1);
    cudaGetSymbolAddress((void**)&p_t1, g_t1);
    cudaGetSymbolAddress((void**)&p_s2, g_s2);
    cudaGetSymbolAddress((void**)&p_t2, g_t2);

    k_setup<<<1, 256>>>(snv, dnv, bq, bk, bv, bm, b1, g1, be1, rm1, rv1,
                        g2, be2, rm2, rv2, W1);
    k_convert<<<TOTAL * 256 / 8 / 256, 256>>>(src_h, dst_h);
    k_prep<<<256, 256>>>(Wk, Wv, Wq, W1, W2, Wm);

    // W1bp = W1b @ Wm  (tensor-core GEMM, M=256 N=128 K=128, zero bias)
    k_gemm<0, true><<<dim3(2, 2), 256>>>(p_W1bb, 128, p_WmT, p_zero,
                                         p_W1bp, 128, nullptr, 0, nullptr, nullptr);

    // G1: kv = src @ [Wk;Wv]'.T    (bf16 out, head-major)
    k_gemm<0, true><<<dim3(192, 4), 256>>>(p_csrc, 256, p_Wkv, p_bkvp,
                                           p_kv, 256, nullptr, 0, nullptr, nullptr);
    // G2 fused: q | y1a = dst @ [Wq;W1a].T  (MODE 3)
    k_gemm<3, true><<<dim3(192, 6), 256>>>(p_cdst, 256, p_Wqy, p_bqy,
                                           p_q, 128, nullptr, 0, nullptr, nullptr,
                                           p_y1a);
    // A: msg = attention(q, k, v)  (bf16 out, head-major)
    k_attn<<<dim3(8, NSEG), 256>>>();
    // G3: x1 = relu((msg @ W1bp'.T + y1a) * s1 + t1)  (bf16 out)
    k_gemm<1, true><<<dim3(192, 4), 256>>>(p_msg, 128, p_W1bp, nullptr,
                                           p_x1, 256, p_y1a, 256, p_s1, p_t1);
    // G4: out = (x1 @ W2.T + b2) * s2 + t2 + dst_h    (fp32 out)
    k_gemm<2, false><<<dim3(192, 4), 256>>>(p_x1, 256, p_W2b, b2,
                                            out, 256, dst_h, 256, p_s2, p_t2);
}

// round 16
// speedup vs baseline: 1.1109x; 1.0136x over previous
#include <cuda_runtime.h>
#include <cuda_bf16.h>
#include <cstdint>

#define TOTAL 24576
#define NSEG  64

// ------------------------- device scratch (static) -------------------------
__device__ __nv_bfloat16 g_csrc[TOTAL * 256];
__device__ __nv_bfloat16 g_cdst[TOTAL * 256];
__device__ __nv_bfloat16 g_kv  [TOTAL * 256];   // head-major k|v, bf16
__device__ __nv_bfloat16 g_q   [TOTAL * 128];   // head-major q, bf16
__device__ float         g_y1a [TOTAL * 256];   // dst_h @ W1a.T + b1'
__device__ __nv_bfloat16 g_msg [TOTAL * 128];   // head-major attention out
__device__ __nv_bfloat16 g_x1  [TOTAL * 256];
__device__ __nv_bfloat16 g_Wkv [256 * 256];
__device__ __nv_bfloat16 g_Wqy [384 * 256];     // [Wq(perm); W1a]
__device__ __nv_bfloat16 g_W1bb[256 * 128];     // bf16 W1b (A of W1bp GEMM)
__device__ __nv_bfloat16 g_WmT [128 * 128];     // bf16 Wm^T, head-major rows
__device__ __nv_bfloat16 g_W1bp[256 * 128];
__device__ __nv_bfloat16 g_W2b [256 * 256];
__device__ float g_bkvp[256], g_bqy[384];
__device__ float g_zero[128];                   // stays 0 (.bss)
__device__ float g_s1[256], g_t1[256], g_s2[256], g_t2[256];
__device__ int g_soff[NSEG + 1], g_doff[NSEG + 1], g_scnt[NSEG], g_dcnt[NSEG];

__device__ __forceinline__ int permc(int n) { return (n & 31) * 4 + (n >> 5); }

// ------------------------------ PTX helpers --------------------------------
__device__ __forceinline__ void ldsm4(uint32_t& r0, uint32_t& r1, uint32_t& r2,
                                      uint32_t& r3, uint32_t a) {
    asm volatile("ldmatrix.sync.aligned.m8n8.x4.shared.b16 {%0,%1,%2,%3}, [%4];"
                 : "=r"(r0), "=r"(r1), "=r"(r2), "=r"(r3) : "r"(a));
}
__device__ __forceinline__ void ldsm4t(uint32_t& r0, uint32_t& r1, uint32_t& r2,
                                       uint32_t& r3, uint32_t a) {
    asm volatile("ldmatrix.sync.aligned.m8n8.x4.trans.shared.b16 {%0,%1,%2,%3}, [%4];"
                 : "=r"(r0), "=r"(r1), "=r"(r2), "=r"(r3) : "r"(a));
}
__device__ __forceinline__ void mma_bf16(float c[4], const uint32_t a[4],
                                         const uint32_t b[2]) {
    asm volatile(
        "mma.sync.aligned.m16n8k16.row.col.f32.bf16.bf16.f32 "
        "{%0,%1,%2,%3},{%4,%5,%6,%7},{%8,%9},{%0,%1,%2,%3};"
        : "+f"(c[0]), "+f"(c[1]), "+f"(c[2]), "+f"(c[3])
        : "r"(a[0]), "r"(a[1]), "r"(a[2]), "r"(a[3]), "r"(b[0]), "r"(b[1]));
}
__device__ __forceinline__ float ex2(float x) {
    float r; asm("ex2.approx.f32 %0, %1;" : "=f"(r) : "f"(x)); return r;
}
__device__ __forceinline__ uint32_t pk(float a, float b) {
    __nv_bfloat162 v = __floats2bfloat162_rn(a, b);
    return *reinterpret_cast<uint32_t*>(&v);
}
__device__ __forceinline__ void cpa16(uint32_t s, const void* g) {
    asm volatile("cp.async.cg.shared.global [%0], [%1], 16;" :: "r"(s), "l"(g));
}
__device__ __forceinline__ void cpa_commit() {
    asm volatile("cp.async.commit_group;" ::: "memory");
}
template<int N>
__device__ __forceinline__ void cpa_wait() {
    asm volatile("cp.async.wait_group %0;" :: "n"(N) : "memory");
}

// ------------------------------- K0: setup ---------------------------------
__device__ __forceinline__ int read_count(const void* p, int i, bool is64) {
    if (is64) return (int)((const long long*)p)[i];
    return ((const int*)p)[i];
}

__global__ void k_setup(const void* snv, const void* dnv,
                        const float* __restrict__ bq, const float* __restrict__ bk,
                        const float* __restrict__ bv, const float* __restrict__ bm,
                        const float* __restrict__ b1,
                        const float* __restrict__ g1, const float* __restrict__ be1,
                        const float* __restrict__ rm1, const float* __restrict__ rv1,
                        const float* __restrict__ g2, const float* __restrict__ be2,
                        const float* __restrict__ rm2, const float* __restrict__ rv2,
                        const float* __restrict__ W1)
{
    int t = threadIdx.x;
    bool s64 = (((const int*)snv)[1] == 0);
    bool d64 = (((const int*)dnv)[1] == 0);
    __shared__ int sc[NSEG], dc[NSEG];
    if (t < NSEG) {
        sc[t] = read_count(snv, t, s64);
        dc[t] = read_count(dnv, t, d64);
    }
    __syncthreads();
    if (t == 0) {
        int ss = 0, dd = 0;
        for (int i = 0; i < NSEG; i++) {
            g_soff[i] = ss; g_doff[i] = dd;
            g_scnt[i] = sc[i]; g_dcnt[i] = dc[i];
            ss += sc[i]; dd += dc[i];
        }
        g_soff[NSEG] = ss; g_doff[NSEG] = dd;
    }
    {
        float s1v = g1[t] * rsqrtf(rv1[t] + 1e-5f);
        g_s1[t] = s1v; g_t1[t] = be1[t] - rm1[t] * s1v;
        float s2v = g2[t] * rsqrtf(rv2[t] + 1e-5f);
        g_s2[t] = s2v; g_t2[t] = be2[t] - rm2[t] * s2v;
    }
    if (t < 128) g_bqy[t] = bq[permc(t)];
    g_bkvp[t] = (t < 128) ? bk[permc(t)] : bv[permc(t - 128)];
    {   // b1' = b1 + W1b @ bm -> g_bqy[128 + t]
        float acc = b1[t];
        const float* wrow = W1 + t * 384 + 256;
        #pragma unroll 8
        for (int j = 0; j < 128; j++) acc += wrow[j] * bm[j];
        g_bqy[128 + t] = acc;
    }
}

// ---------------------- fp32 -> bf16 activation convert --------------------
__global__ void k_convert(const float* __restrict__ s, const float* __restrict__ d)
{
    int i = blockIdx.x * blockDim.x + threadIdx.x;   // over TOTAL*256/8
    const float4* s4 = (const float4*)s;
    const float4* d4 = (const float4*)d;
    float4 a = s4[2 * i], b = s4[2 * i + 1];
    uint4 o;
    o.x = pk(a.x, a.y); o.y = pk(a.z, a.w); o.z = pk(b.x, b.y); o.w = pk(b.z, b.w);
    ((uint4*)g_csrc)[i] = o;
    a = d4[2 * i]; b = d4[2 * i + 1];
    o.x = pk(a.x, a.y); o.y = pk(a.z, a.w); o.z = pk(b.x, b.y); o.w = pk(b.z, b.w);
    ((uint4*)g_cdst)[i] = o;
}

// ------------------------ weight conversion + permute ----------------------
__global__ void k_prep(const float* __restrict__ Wk, const float* __restrict__ Wv,
                       const float* __restrict__ Wq, const float* __restrict__ W1,
                       const float* __restrict__ W2, const float* __restrict__ Wm)
{
    int i = blockIdx.x * blockDim.x + threadIdx.x;   // 65536 threads
    {
        int n = i >> 8, k = i & 255;
        float v = (n < 128) ? Wk[permc(n) * 256 + k] : Wv[permc(n - 128) * 256 + k];
        g_Wkv[i] = __float2bfloat16(v);
    }
    // Wqy = [Wq(perm rows); W1a] : 384 x 256 (strided, 2 passes)
    #pragma unroll
    for (int pass = 0; pass < 2; pass++) {
        int j = i + pass * 65536;
        if (j < 384 * 256) {
            int n = j >> 8, k = j & 255;
            float v = (n < 128) ? Wq[permc(n) * 256 + k] : W1[(n - 128) * 384 + k];
            g_Wqy[j] = __float2bfloat16(v);
        }
    }
    g_W2b[i] = __float2bfloat16(W2[i]);
    // W1b -> bf16 (A operand of the W1bp GEMM)
    if (i < 256 * 128) {
        int n = i >> 7, k = i & 127;
        g_W1bb[i] = __float2bfloat16(W1[n * 384 + 256 + k]);
    }
    // Wm^T with head-major column permute folded into rows
    if (i < 128 * 128) {
        int j = i >> 7, cp = i & 127;
        int co = (cp & 3) * 32 + (cp >> 2);
        g_WmT[co * 128 + j] = __float2bfloat16(Wm[i]);
    }
}

// ------------------------------ bf16 MMA GEMM ------------------------------
// C[M,N] = A[M,K](bf16) @ W[N,K](bf16)^T + epilogue. 128x64 block, BK=32,
// 256 thr = 8 warps (4m x 2n), warp tile 32x32. 3-stage cp.async pipeline.
// MODE 0: acc + bias                MODE 1: relu((acc+aux)*s+t)
// MODE 2: (acc+bias)*s+t+aux       MODE 3: n0<128 -> bf16 Cv (ld 128),
//                                          n0>=128 -> fp32 C2 (ld 256, c-128)
template<int MODE, bool OBF>
__global__ __launch_bounds__(256) void k_gemm(
    const __nv_bfloat16* __restrict__ A, int K,
    const __nv_bfloat16* __restrict__ W,
    const float* __restrict__ bias,
    void* __restrict__ Cv, int N,
    const float* __restrict__ aux, int auxLd,
    const float* __restrict__ sbn, const float* __restrict__ tbn,
    float* __restrict__ C2 = nullptr)
{
    constexpr int ST = 3;
    __shared__ __align__(16) __nv_bfloat16 As[ST][128 * 32];
    __shared__ __align__(16) __nv_bfloat16 Bs[ST][64 * 32];
    const int t = threadIdx.x, lane = t & 31, w = t >> 5;
    const int mw = w >> 1, nw = w & 1;
    const int m0 = blockIdx.x * 128, n0 = blockIdx.y * 64;

    const int rA = t >> 2, kc = t & 3;
    const int swz = kc ^ ((rA >> 1) & 3);
    const __nv_bfloat16* Ag0 = A + (size_t)(m0 + rA) * K + kc * 8;
    const __nv_bfloat16* Ag1 = Ag0 + (size_t)64 * K;
    const __nv_bfloat16* Wg  = W + (size_t)(n0 + rA) * K + kc * 8;
    const int oA0 = (rA * 4 + swz) * 8;
    const int oA1 = ((rA + 64) * 4 + swz) * 8;
    const int oB  = (rA * 4 + swz) * 8;
    const uint32_t baseA = (uint32_t)__cvta_generic_to_shared(As);
    const uint32_t baseB = (uint32_t)__cvta_generic_to_shared(Bs);

    const int nIter = K >> 5;

    #pragma unroll
    for (int s = 0; s < ST - 1; s++) {
        if (s < nIter) {
            cpa16(baseA + (s * 128 * 32 + oA0) * 2, Ag0 + s * 32);
            cpa16(baseA + (s * 128 * 32 + oA1) * 2, Ag1 + s * 32);
            cpa16(baseB + (s * 64 * 32 + oB) * 2,  Wg  + s * 32);
        }
        cpa_commit();
    }

    float acc[2][4][4] = {};
    int stage = 0;
    for (int i = 0; i < nIter; i++) {
        cpa_wait<ST - 2>();
        __syncthreads();
        {
            const int nx = i + ST - 1;
            if (nx < nIter) {
                const int sb = (stage + ST - 1) % ST;
                cpa16(baseA + (sb * 128 * 32 + oA0) * 2, Ag0 + nx * 32);
                cpa16(baseA + (sb * 128 * 32 + oA1) * 2, Ag1 + nx * 32);
                cpa16(baseB + (sb * 64 * 32 + oB) * 2,  Wg  + nx * 32);
            }
            cpa_commit();
        }
        const uint32_t bA = baseA + stage * (128 * 32 * 2);
        const uint32_t bB = baseB + stage * (64 * 32 * 2);
        #pragma unroll
        for (int kk = 0; kk < 2; kk++) {
            uint32_t af[2][4];
            #pragma unroll
            for (int f = 0; f < 2; f++) {
                int row = mw * 32 + f * 16 + (lane & 15);
                int c8 = (kk * 2 + (lane >> 4)) ^ ((row >> 1) & 3);
                ldsm4(af[f][0], af[f][1], af[f][2], af[f][3],
                      bA + (row * 4 + c8) * 16);
            }
            uint32_t bfr[2][4];
            #pragma unroll
            for (int p = 0; p < 2; p++) {
                int row = nw * 32 + p * 16 + (lane & 7) + ((lane >> 4) << 3);
                int c8 = (kk * 2 + ((lane >> 3) & 1)) ^ ((row >> 1) & 3);
                ldsm4(bfr[p][0], bfr[p][1], bfr[p][2], bfr[p][3],
                      bB + (row * 4 + c8) * 16);
            }
            #pragma unroll
            for (int f = 0; f < 2; f++)
                #pragma unroll
                for (int n = 0; n < 4; n++)
                    mma_bf16(acc[f][n], af[f], &bfr[n >> 1][(n & 1) * 2]);
        }
        stage = (stage + 1) % ST;
    }

    const int er = m0 + mw * 32 + (lane >> 2);
    const int ec = n0 + nw * 32 + (lane & 3) * 2;
    #pragma unroll
    for (int f = 0; f < 2; f++)
        #pragma unroll
        for (int n = 0; n < 4; n++)
            #pragma unroll
            for (int half = 0; half < 2; half++) {
                int r = er + f * 16 + half * 8;
                int c = ec + n * 8;
                float x0 = acc[f][n][half * 2], x1 = acc[f][n][half * 2 + 1];
                if (MODE == 0) {
                    x0 += bias[c]; x1 += bias[c + 1];
                } else if (MODE == 1) {
                    x0 += aux[(size_t)r * auxLd + c];
                    x1 += aux[(size_t)r * auxLd + c + 1];
                    x0 = fmaxf(x0 * sbn[c] + tbn[c], 0.f);
                    x1 = fmaxf(x1 * sbn[c + 1] + tbn[c + 1], 0.f);
                } else if (MODE == 2) {
                    x0 = (x0 + bias[c]) * sbn[c] + tbn[c] + aux[(size_t)r * auxLd + c];
                    x1 = (x1 + bias[c + 1]) * sbn[c + 1] + tbn[c + 1] +
                         aux[(size_t)r * auxLd + c + 1];
                } else {                               // MODE 3: fused q | y1a
                    x0 += bias[c]; x1 += bias[c + 1];
                    if (n0 < 128) {
                        *(__nv_bfloat162*)((__nv_bfloat16*)Cv + (size_t)r * 128 + c) =
                            __floats2bfloat162_rn(x0, x1);
                    } else {
                        *(float2*)(C2 + (size_t)r * 256 + (c - 128)) =
                            make_float2(x0, x1);
                    }
                    continue;
                }
                if (OBF) {
                    __nv_bfloat162 h = __floats2bfloat162_rn(x0, x1);
                    *(__nv_bfloat162*)((__nv_bfloat16*)Cv + (size_t)r * N + c) = h;
                } else {
                    *(float2*)((float*)Cv + (size_t)r * N + c) = make_float2(x0, x1);
                }
            }
}

// ------------------------------- Attention ---------------------------------
// Block: 64 dst rows of one segment; 8 warps = 4 heads x 2 q-halves.
// KV tiles now double-buffered via cp.async: tile tt+1 streams in while
// tile tt is computed (QK mma + softmax + PV mma).
__global__ __launch_bounds__(256) void k_attn()
{
    __shared__ __align__(16) __nv_bfloat16 qs[64 * 128];
    __shared__ __align__(16) __nv_bfloat16 ks[2][32 * 256];
    const int b = blockIdx.y, q0 = blockIdx.x * 64;
    const int nd = g_dcnt[b];
    if (q0 >= nd) return;
    const int ns = g_scnt[b], soff = g_soff[b], doff = g_doff[b];
    const int nQ = min(64, nd - q0);
    const int t = threadIdx.x, lane = t & 31, w = t >> 5;
    const int h = w & 3, qh = w >> 2;

    const uint32_t baseQ = (uint32_t)__cvta_generic_to_shared(qs);
    const uint32_t baseK = (uint32_t)__cvta_generic_to_shared(ks);
    const int nT = (ns + 31) >> 5;

    // per-thread kv-tile slice: row = t>>3 .. (+?), use idx layout: 4 lines each
    const int kr = t >> 3, kcc = (t & 7) * 4;   // rows 0..31, col-chunks 0..31 in 4s
    // prologue: issue tile 0 into buffer 0
    #pragma unroll
    for (int i = 0; i < 4; i++) {
        int row = kr, c = kcc + i;
        int gr = soff + row; if (gr >= TOTAL) gr = TOTAL - 1;
        cpa16(baseK + ((row * 32 + (c ^ (row & 7))) * 8) * 2,
              g_kv + (size_t)gr * 256 + c * 8);
    }
    cpa_commit();

    // q tile staging (synchronous; overlaps tile-0 flight)
    #pragma unroll
    for (int i = 0; i < 4; i++) {
        int idx = t + i * 256;
        int row = idx >> 4, c = idx & 15;
        uint4 v = make_uint4(0, 0, 0, 0);
        if (row < nQ)
            v = *(const uint4*)(g_q + (size_t)(doff + q0 + row) * 128 + c * 8);
        *(uint4*)(qs + (row * 16 + (c ^ (row & 7))) * 8) = v;
    }

    float acc[2][4][4] = {};
    float den[2][2] = {};
    const float sc2 = 0.25504167f;   // log2(e)/sqrt(32)

    for (int tt = 0; tt < nT; tt++) {
        const int s0 = tt * 32;
        __syncthreads();             // readers of buf[(tt+1)&1] (iter tt-1) done;
                                     // also q staging visible at tt==0
        if (tt + 1 < nT) {           // issue tile tt+1 into buf[(tt+1)&1]
            const uint32_t bufO = ((tt + 1) & 1) * (32 * 256 * 2);
            #pragma unroll
            for (int i = 0; i < 4; i++) {
                int row = kr, c = kcc + i;
                int gr = soff + (tt + 1) * 32 + row; if (gr >= TOTAL) gr = TOTAL - 1;
                cpa16(baseK + bufO + ((row * 32 + (c ^ (row & 7))) * 8) * 2,
                      g_kv + (size_t)gr * 256 + c * 8);
            }
        }
        cpa_commit();
        cpa_wait<1>();               // tile tt resident (tt+1 may be in flight)
        __syncthreads();             // cross-thread visibility of tile tt

        const uint32_t bK = baseK + (tt & 1) * (32 * 256 * 2);

        // ---- S = Q K^T (per head, K=32) ----
        float S[2][4][4] = {};
        #pragma unroll
        for (int kk = 0; kk < 2; kk++) {
            uint32_t af[2][4];
            #pragma unroll
            for (int f = 0; f < 2; f++) {
                int row = qh * 32 + f * 16 + (lane & 15);
                int c8 = (h * 4 + kk * 2 + (lane >> 4)) ^ (row & 7);
                ldsm4(af[f][0], af[f][1], af[f][2], af[f][3],
                      baseQ + (row * 16 + c8) * 16);
            }
            uint32_t bk2[2][4];
            #pragma unroll
            for (int p = 0; p < 2; p++) {
                int row = p * 16 + (lane & 7) + ((lane >> 4) << 3);
                int c8 = (h * 4 + kk * 2 + ((lane >> 3) & 1)) ^ (row & 7);
                ldsm4(bk2[p][0], bk2[p][1], bk2[p][2], bk2[p][3],
                      bK + (row * 32 + c8) * 16);
            }
            #pragma unroll
            for (int f = 0; f < 2; f++)
                #pragma unroll
                for (int n = 0; n < 4; n++)
                    mma_bf16(S[f][n], af[f], &bk2[n >> 1][(n & 1) * 2]);
        }

        // ---- exp + mask + den, pack P into A fragments ----
        uint32_t Ap[2][2][4];
        #pragma unroll
        for (int f = 0; f < 2; f++) {
            float d0 = 0.f, d1 = 0.f;
            #pragma unroll
            for (int n = 0; n < 4; n++) {
                int cb = s0 + n * 8 + (lane & 3) * 2;
                float e0 = ex2(S[f][n][0] * sc2); if (cb >= ns) e0 = 0.f;
                float e1 = ex2(S[f][n][1] * sc2); if (cb + 1 >= ns) e1 = 0.f;
                float e2 = ex2(S[f][n][2] * sc2); if (cb >= ns) e2 = 0.f;
                float e3 = ex2(S[f][n][3] * sc2); if (cb + 1 >= ns) e3 = 0.f;
                d0 += e0 + e1; d1 += e2 + e3;
                Ap[f][n >> 1][(n & 1) * 2]     = pk(e0, e1);
                Ap[f][n >> 1][(n & 1) * 2 + 1] = pk(e2, e3);
            }
            den[f][0] += d0; den[f][1] += d1;
        }

        // ---- O += P V (V B-frags via ldmatrix.trans) ----
        #pragma unroll
        for (int kk = 0; kk < 2; kk++) {
            uint32_t bv[2][4];
            #pragma unroll
            for (int p = 0; p < 2; p++) {
                int row = kk * 16 + (lane & 15);
                int c8 = (16 + h * 4 + p * 2 + (lane >> 4)) ^ (row & 7);
                ldsm4t(bv[p][0], bv[p][1], bv[p][2], bv[p][3],
                       bK + (row * 32 + c8) * 16);
            }
            #pragma unroll
            for (int f = 0; f < 2; f++)
                #pragma unroll
                for (int n = 0; n < 4; n++)
                    mma_bf16(acc[f][n], Ap[f][kk], &bv[n >> 1][(n & 1) * 2]);
        }
    }

    #pragma unroll
    for (int f = 0; f < 2; f++)
        #pragma unroll
        for (int u = 0; u < 2; u++) {
            float v = den[f][u];
            v += __shfl_xor_sync(0xffffffffu, v, 1);
            v += __shfl_xor_sync(0xffffffffu, v, 2);
            den[f][u] = 1.f / v;
        }

    #pragma unroll
    for (int f = 0; f < 2; f++)
        #pragma unroll
        for (int n = 0; n < 4; n++)
            #pragma unroll
            for (int half = 0; half < 2; half++) {
                int rl = qh * 32 + f * 16 + (lane >> 2) + half * 8;
                if (rl < nQ) {
                    float inv = den[f][half];
                    __nv_bfloat162 o = __floats2bfloat162_rn(
                        acc[f][n][half * 2] * inv, acc[f][n][half * 2 + 1] * inv);
                    *(__nv_bfloat162*)(g_msg + (size_t)(doff + q0 + rl) * 128 +
                                       h * 32 + n * 8 + (lane & 3) * 2) = o;
                }
            }
}

// ------------------------------- launcher ----------------------------------
extern "C" void kernel_launch(void* const* d_in, const int* in_sizes, int n_in,
                              void* d_out, int out_size)
{
    const float* src_h = (const float*)d_in[0];
    const float* dst_h = (const float*)d_in[1];
    const void*  snv   = d_in[2];
    const void*  dnv   = d_in[3];
    const float* Wq = (const float*)d_in[4];  const float* bq = (const float*)d_in[5];
    const float* Wk = (const float*)d_in[6];  const float* bk = (const float*)d_in[7];
    const float* Wv = (const float*)d_in[8];  const float* bv = (const float*)d_in[9];
    const float* Wm = (const float*)d_in[10]; const float* bm = (const float*)d_in[11];
    const float* W1 = (const float*)d_in[12]; const float* b1 = (const float*)d_in[13];
    const float* g1 = (const float*)d_in[14]; const float* be1 = (const float*)d_in[15];
    const float* rm1 = (const float*)d_in[16]; const float* rv1 = (const float*)d_in[17];
    const float* W2 = (const float*)d_in[18]; const float* b2 = (const float*)d_in[19];
    const float* g2 = (const float*)d_in[20]; const float* be2 = (const float*)d_in[21];
    const float* rm2 = (const float*)d_in[22]; const float* rv2 = (const float*)d_in[23];
    float* out = (float*)d_out;

    __nv_bfloat16 *p_csrc, *p_cdst, *p_kv, *p_q, *p_msg, *p_x1;
    __nv_bfloat16 *p_Wkv, *p_Wqy, *p_W1bb, *p_WmT, *p_W1bp, *p_W2b;
    float *p_y1a, *p_bkvp, *p_bqy, *p_zero, *p_s1, *p_t1, *p_s2, *p_t2;
    cudaGetSymbolAddress((void**)&p_csrc, g_csrc);
    cudaGetSymbolAddress((void**)&p_cdst, g_cdst);
    cudaGetSymbolAddress((void**)&p_kv, g_kv);
    cudaGetSymbolAddress((void**)&p_q, g_q);
    cudaGetSymbolAddress((void**)&p_y1a, g_y1a);
    cudaGetSymbolAddress((void**)&p_msg, g_msg);
    cudaGetSymbolAddress((void**)&p_x1, g_x1);
    cudaGetSymbolAddress((void**)&p_Wkv, g_Wkv);
    cudaGetSymbolAddress((void**)&p_Wqy, g_Wqy);
    cudaGetSymbolAddress((void**)&p_W1bb, g_W1bb);
    cudaGetSymbolAddress((void**)&p_WmT, g_WmT);
    cudaGetSymbolAddress((void**)&p_W1bp, g_W1bp);
    cudaGetSymbolAddress((void**)&p_W2b, g_W2b);
    cudaGetSymbolAddress((void**)&p_bkvp, g_bkvp);
    cudaGetSymbolAddress((void**)&p_bqy, g_bqy);
    cudaGetSymbolAddress((void**)&p_zero, g_zero);
    cudaGetSymbolAddress((void**)&p_s1, g_s1);
    cudaGetSymbolAddress((void**)&p_t1, g_t1);
    cudaGetSymbolAddress((void**)&p_s2, g_s2);
    cudaGetSymbolAddress((void**)&p_t2, g_t2);

    k_setup<<<1, 256>>>(snv, dnv, bq, bk, bv, bm, b1, g1, be1, rm1, rv1,
                        g2, be2, rm2, rv2, W1);
    k_convert<<<TOTAL * 256 / 8 / 256, 256>>>(src_h, dst_h);
    k_prep<<<256, 256>>>(Wk, Wv, Wq, W1, W2, Wm);

    // W1bp = W1b @ Wm  (tensor-core GEMM, M=256 N=128 K=128, zero bias)
    k_gemm<0, true><<<dim3(2, 2), 256>>>(p_W1bb, 128, p_WmT, p_zero,
                                         p_W1bp, 128, nullptr, 0, nullptr, nullptr);

    // G1: kv = src @ [Wk;Wv]'.T    (bf16 out, head-major)
    k_gemm<0, true><<<dim3(192, 4), 256>>>(p_csrc, 256, p_Wkv, p_bkvp,
                                           p_kv, 256, nullptr, 0, nullptr, nullptr);
    // G2 fused: q | y1a = dst @ [Wq;W1a].T  (MODE 3)
    k_gemm<3, true><<<dim3(192, 6), 256>>>(p_cdst, 256, p_Wqy, p_bqy,
                                           p_q, 128, nullptr, 0, nullptr, nullptr,
                                           p_y1a);
    // A: msg = attention(q, k, v)  (bf16 out, head-major)
    k_attn<<<dim3(8, NSEG), 256>>>();
    // G3: x1 = relu((msg @ W1bp'.T + y1a) * s1 + t1)  (bf16 out)
    k_gemm<1, true><<<dim3(192, 4), 256>>>(p_msg, 128, p_W1bp, nullptr,
                                           p_x1, 256, p_y1a, 256, p_s1, p_t1);
    // G4: out = (x1 @ W2.T + b2) * s2 + t2 + dst_h    (fp32 out)
    k_gemm<2, false><<<dim3(192, 4), 256>>>(p_x1, 256, p_W2b, b2,
                                            out, 256, dst_h, 256, p_s2, p_t2);
}

// round 17
// speedup vs baseline: 1.1858x; 1.0674x over previous
#include <cuda_runtime.h>
#include <cuda_bf16.h>
#include <cstdint>

#define TOTAL 24576
#define NSEG  64

// ------------------------- device scratch (static) -------------------------
__device__ __nv_bfloat16 g_csrc[TOTAL * 256];
__device__ __nv_bfloat16 g_cdst[TOTAL * 256];
__device__ __nv_bfloat16 g_kv  [TOTAL * 256];   // head-major k|v, bf16
__device__ __nv_bfloat16 g_q   [TOTAL * 128];   // head-major q, bf16
__device__ float         g_y1a [TOTAL * 256];   // dst_h @ W1a.T + b1'
__device__ __nv_bfloat16 g_msg [TOTAL * 128];   // head-major attention out
__device__ __nv_bfloat16 g_x1  [TOTAL * 256];
__device__ __nv_bfloat16 g_Wkv [256 * 256];
__device__ __nv_bfloat16 g_Wqy [384 * 256];     // [Wq(perm); W1a]
__device__ __nv_bfloat16 g_W1bb[256 * 128];     // bf16 W1b (A of W1bp GEMM)
__device__ __nv_bfloat16 g_WmT [128 * 128];     // bf16 Wm^T, head-major rows
__device__ __nv_bfloat16 g_W1bp[256 * 128];
__device__ __nv_bfloat16 g_W2b [256 * 256];
__device__ float g_bkvp[256], g_bqy[384];
__device__ float g_zero[128];                   // stays 0 (.bss)
__device__ float g_s1[256], g_t1[256], g_s2[256], g_t2[256];
__device__ int g_soff[NSEG + 1], g_doff[NSEG + 1], g_scnt[NSEG], g_dcnt[NSEG];

__device__ __forceinline__ int permc(int n) { return (n & 31) * 4 + (n >> 5); }

// ------------------------------ PTX helpers --------------------------------
__device__ __forceinline__ void ldsm4(uint32_t& r0, uint32_t& r1, uint32_t& r2,
                                      uint32_t& r3, uint32_t a) {
    asm volatile("ldmatrix.sync.aligned.m8n8.x4.shared.b16 {%0,%1,%2,%3}, [%4];"
                 : "=r"(r0), "=r"(r1), "=r"(r2), "=r"(r3) : "r"(a));
}
__device__ __forceinline__ void ldsm4t(uint32_t& r0, uint32_t& r1, uint32_t& r2,
                                       uint32_t& r3, uint32_t a) {
    asm volatile("ldmatrix.sync.aligned.m8n8.x4.trans.shared.b16 {%0,%1,%2,%3}, [%4];"
                 : "=r"(r0), "=r"(r1), "=r"(r2), "=r"(r3) : "r"(a));
}
__device__ __forceinline__ void mma_bf16(float c[4], const uint32_t a[4],
                                         const uint32_t b[2]) {
    asm volatile(
        "mma.sync.aligned.m16n8k16.row.col.f32.bf16.bf16.f32 "
        "{%0,%1,%2,%3},{%4,%5,%6,%7},{%8,%9},{%0,%1,%2,%3};"
        : "+f"(c[0]), "+f"(c[1]), "+f"(c[2]), "+f"(c[3])
        : "r"(a[0]), "r"(a[1]), "r"(a[2]), "r"(a[3]), "r"(b[0]), "r"(b[1]));
}
__device__ __forceinline__ float ex2(float x) {
    float r; asm("ex2.approx.f32 %0, %1;" : "=f"(r) : "f"(x)); return r;
}
__device__ __forceinline__ uint32_t pk(float a, float b) {
    __nv_bfloat162 v = __floats2bfloat162_rn(a, b);
    return *reinterpret_cast<uint32_t*>(&v);
}
__device__ __forceinline__ void cpa16(uint32_t s, const void* g) {
    asm volatile("cp.async.cg.shared.global [%0], [%1], 16;" :: "r"(s), "l"(g));
}
__device__ __forceinline__ void cpa_commit() {
    asm volatile("cp.async.commit_group;" ::: "memory");
}
template<int N>
__device__ __forceinline__ void cpa_wait() {
    asm volatile("cp.async.wait_group %0;" :: "n"(N) : "memory");
}

__device__ __forceinline__ int read_count(const void* p, int i, bool is64) {
    if (is64) return (int)((const long long*)p)[i];
    return ((const int*)p)[i];
}

// -------------------- K0: fused front (setup|prep|convert) -----------------
// grid 3329 x 256:
//   b == 0      : counts/offsets, BN->affine, biases (setup)
//   b 1..256    : weight conversion + permutes (prep), i = (b-1)*256+t
//   b 257..3328 : fp32->bf16 activation convert, i = (b-257)*256+t
__global__ void k_front(const void* snv, const void* dnv,
                        const float* __restrict__ src_h,
                        const float* __restrict__ dst_h,
                        const float* __restrict__ Wq, const float* __restrict__ bq,
                        const float* __restrict__ Wk, const float* __restrict__ bk,
                        const float* __restrict__ Wv, const float* __restrict__ bv,
                        const float* __restrict__ Wm, const float* __restrict__ bm,
                        const float* __restrict__ W1, const float* __restrict__ b1,
                        const float* __restrict__ g1, const float* __restrict__ be1,
                        const float* __restrict__ rm1, const float* __restrict__ rv1,
                        const float* __restrict__ W2, const float* __restrict__ b2u,
                        const float* __restrict__ g2, const float* __restrict__ be2,
                        const float* __restrict__ rm2, const float* __restrict__ rv2)
{
    const int b = blockIdx.x, t = threadIdx.x;
    if (b >= 257) {
        // -------- activation convert --------
        const int i = (b - 257) * 256 + t;           // [0, 786432)
        const float4* s4 = (const float4*)src_h;
        const float4* d4 = (const float4*)dst_h;
        float4 a = s4[2 * i], c = s4[2 * i + 1];
        uint4 o;
        o.x = pk(a.x, a.y); o.y = pk(a.z, a.w); o.z = pk(c.x, c.y); o.w = pk(c.z, c.w);
        ((uint4*)g_csrc)[i] = o;
        a = d4[2 * i]; c = d4[2 * i + 1];
        o.x = pk(a.x, a.y); o.y = pk(a.z, a.w); o.z = pk(c.x, c.y); o.w = pk(c.z, c.w);
        ((uint4*)g_cdst)[i] = o;
        return;
    }
    if (b == 0) {
        // -------- setup --------
        bool s64 = (((const int*)snv)[1] == 0);
        bool d64 = (((const int*)dnv)[1] == 0);
        __shared__ int sc[NSEG], dc[NSEG];
        if (t < NSEG) {
            sc[t] = read_count(snv, t, s64);
            dc[t] = read_count(dnv, t, d64);
        }
        __syncthreads();
        if (t == 0) {
            int ss = 0, dd = 0;
            for (int i = 0; i < NSEG; i++) {
                g_soff[i] = ss; g_doff[i] = dd;
                g_scnt[i] = sc[i]; g_dcnt[i] = dc[i];
                ss += sc[i]; dd += dc[i];
            }
            g_soff[NSEG] = ss; g_doff[NSEG] = dd;
        }
        {
            float s1v = g1[t] * rsqrtf(rv1[t] + 1e-5f);
            g_s1[t] = s1v; g_t1[t] = be1[t] - rm1[t] * s1v;
            float s2v = g2[t] * rsqrtf(rv2[t] + 1e-5f);
            g_s2[t] = s2v; g_t2[t] = be2[t] - rm2[t] * s2v;
        }
        if (t < 128) g_bqy[t] = bq[permc(t)];
        g_bkvp[t] = (t < 128) ? bk[permc(t)] : bv[permc(t - 128)];
        {   // b1' = b1 + W1b @ bm -> g_bqy[128 + t]
            float acc = b1[t];
            const float* wrow = W1 + t * 384 + 256;
            #pragma unroll 8
            for (int j = 0; j < 128; j++) acc += wrow[j] * bm[j];
            g_bqy[128 + t] = acc;
        }
        return;
    }
    // -------- weight prep --------
    const int i = (b - 1) * 256 + t;                 // [0, 65536)
    {
        int n = i >> 8, k = i & 255;
        float v = (n < 128) ? Wk[permc(n) * 256 + k] : Wv[permc(n - 128) * 256 + k];
        g_Wkv[i] = __float2bfloat16(v);
    }
    #pragma unroll
    for (int pass = 0; pass < 2; pass++) {
        int j = i + pass * 65536;
        if (j < 384 * 256) {
            int n = j >> 8, k = j & 255;
            float v = (n < 128) ? Wq[permc(n) * 256 + k] : W1[(n - 128) * 384 + k];
            g_Wqy[j] = __float2bfloat16(v);
        }
    }
    g_W2b[i] = __float2bfloat16(W2[i]);
    if (i < 256 * 128) {
        int n = i >> 7, k = i & 127;
        g_W1bb[i] = __float2bfloat16(W1[n * 384 + 256 + k]);
    }
    if (i < 128 * 128) {
        int j = i >> 7, cp = i & 127;
        int co = (cp & 3) * 32 + (cp >> 2);
        g_WmT[co * 128 + j] = __float2bfloat16(Wm[i]);
    }
}

// ------------------------------ bf16 MMA GEMM ------------------------------
// C[M,N] = A[M,K](bf16) @ W[N,K](bf16)^T + epilogue. 128x64 block, BK=32,
// 256 thr = 8 warps (4m x 2n), warp tile 32x32. 3-stage cp.async pipeline.
// MODE 0: acc + bias                MODE 1: relu((acc+aux)*s+t)
// MODE 2: (acc+bias)*s+t+aux       MODE 3: n0<128 -> bf16 Cv (ld 128),
//                                          n0>=128 -> fp32 C2 (ld 256, c-128)
template<int MODE, bool OBF>
__global__ __launch_bounds__(256) void k_gemm(
    const __nv_bfloat16* __restrict__ A, int K,
    const __nv_bfloat16* __restrict__ W,
    const float* __restrict__ bias,
    void* __restrict__ Cv, int N,
    const float* __restrict__ aux, int auxLd,
    const float* __restrict__ sbn, const float* __restrict__ tbn,
    float* __restrict__ C2 = nullptr)
{
    constexpr int ST = 3;
    __shared__ __align__(16) __nv_bfloat16 As[ST][128 * 32];
    __shared__ __align__(16) __nv_bfloat16 Bs[ST][64 * 32];
    const int t = threadIdx.x, lane = t & 31, w = t >> 5;
    const int mw = w >> 1, nw = w & 1;
    const int m0 = blockIdx.x * 128, n0 = blockIdx.y * 64;

    const int rA = t >> 2, kc = t & 3;
    const int swz = kc ^ ((rA >> 1) & 3);
    const __nv_bfloat16* Ag0 = A + (size_t)(m0 + rA) * K + kc * 8;
    const __nv_bfloat16* Ag1 = Ag0 + (size_t)64 * K;
    const __nv_bfloat16* Wg  = W + (size_t)(n0 + rA) * K + kc * 8;
    const int oA0 = (rA * 4 + swz) * 8;
    const int oA1 = ((rA + 64) * 4 + swz) * 8;
    const int oB  = (rA * 4 + swz) * 8;
    const uint32_t baseA = (uint32_t)__cvta_generic_to_shared(As);
    const uint32_t baseB = (uint32_t)__cvta_generic_to_shared(Bs);

    const int nIter = K >> 5;

    #pragma unroll
    for (int s = 0; s < ST - 1; s++) {
        if (s < nIter) {
            cpa16(baseA + (s * 128 * 32 + oA0) * 2, Ag0 + s * 32);
            cpa16(baseA + (s * 128 * 32 + oA1) * 2, Ag1 + s * 32);
            cpa16(baseB + (s * 64 * 32 + oB) * 2,  Wg  + s * 32);
        }
        cpa_commit();
    }

    float acc[2][4][4] = {};
    int stage = 0;
    for (int i = 0; i < nIter; i++) {
        cpa_wait<ST - 2>();
        __syncthreads();
        {
            const int nx = i + ST - 1;
            if (nx < nIter) {
                const int sb = (stage + ST - 1) % ST;
                cpa16(baseA + (sb * 128 * 32 + oA0) * 2, Ag0 + nx * 32);
                cpa16(baseA + (sb * 128 * 32 + oA1) * 2, Ag1 + nx * 32);
                cpa16(baseB + (sb * 64 * 32 + oB) * 2,  Wg  + nx * 32);
            }
            cpa_commit();
        }
        const uint32_t bA = baseA + stage * (128 * 32 * 2);
        const uint32_t bB = baseB + stage * (64 * 32 * 2);
        #pragma unroll
        for (int kk = 0; kk < 2; kk++) {
            uint32_t af[2][4];
            #pragma unroll
            for (int f = 0; f < 2; f++) {
                int row = mw * 32 + f * 16 + (lane & 15);
                int c8 = (kk * 2 + (lane >> 4)) ^ ((row >> 1) & 3);
                ldsm4(af[f][0], af[f][1], af[f][2], af[f][3],
                      bA + (row * 4 + c8) * 16);
            }
            uint32_t bfr[2][4];
            #pragma unroll
            for (int p = 0; p < 2; p++) {
                int row = nw * 32 + p * 16 + (lane & 7) + ((lane >> 4) << 3);
                int c8 = (kk * 2 + ((lane >> 3) & 1)) ^ ((row >> 1) & 3);
                ldsm4(bfr[p][0], bfr[p][1], bfr[p][2], bfr[p][3],
                      bB + (row * 4 + c8) * 16);
            }
            #pragma unroll
            for (int f = 0; f < 2; f++)
                #pragma unroll
                for (int n = 0; n < 4; n++)
                    mma_bf16(acc[f][n], af[f], &bfr[n >> 1][(n & 1) * 2]);
        }
        stage = (stage + 1) % ST;
    }

    const int er = m0 + mw * 32 + (lane >> 2);
    const int ec = n0 + nw * 32 + (lane & 3) * 2;
    #pragma unroll
    for (int f = 0; f < 2; f++)
        #pragma unroll
        for (int n = 0; n < 4; n++)
            #pragma unroll
            for (int half = 0; half < 2; half++) {
                int r = er + f * 16 + half * 8;
                int c = ec + n * 8;
                float x0 = acc[f][n][half * 2], x1 = acc[f][n][half * 2 + 1];
                if (MODE == 0) {
                    x0 += bias[c]; x1 += bias[c + 1];
                } else if (MODE == 1) {
                    x0 += aux[(size_t)r * auxLd + c];
                    x1 += aux[(size_t)r * auxLd + c + 1];
                    x0 = fmaxf(x0 * sbn[c] + tbn[c], 0.f);
                    x1 = fmaxf(x1 * sbn[c + 1] + tbn[c + 1], 0.f);
                } else if (MODE == 2) {
                    x0 = (x0 + bias[c]) * sbn[c] + tbn[c] + aux[(size_t)r * auxLd + c];
                    x1 = (x1 + bias[c + 1]) * sbn[c + 1] + tbn[c + 1] +
                         aux[(size_t)r * auxLd + c + 1];
                } else {                               // MODE 3: fused q | y1a
                    x0 += bias[c]; x1 += bias[c + 1];
                    if (n0 < 128) {
                        *(__nv_bfloat162*)((__nv_bfloat16*)Cv + (size_t)r * 128 + c) =
                            __floats2bfloat162_rn(x0, x1);
                    } else {
                        *(float2*)(C2 + (size_t)r * 256 + (c - 128)) =
                            make_float2(x0, x1);
                    }
                    continue;
                }
                if (OBF) {
                    __nv_bfloat162 h = __floats2bfloat162_rn(x0, x1);
                    *(__nv_bfloat162*)((__nv_bfloat16*)Cv + (size_t)r * N + c) = h;
                } else {
                    *(float2*)((float*)Cv + (size_t)r * N + c) = make_float2(x0, x1);
                }
            }
}

// ------------------------------- Attention ---------------------------------
// Block: 64 dst rows of one segment; 8 warps = 4 heads x 2 q-halves.
// KV tiles double-buffered via cp.async.
__global__ __launch_bounds__(256) void k_attn()
{
    __shared__ __align__(16) __nv_bfloat16 qs[64 * 128];
    __shared__ __align__(16) __nv_bfloat16 ks[2][32 * 256];
    const int b = blockIdx.y, q0 = blockIdx.x * 64;
    const int nd = g_dcnt[b];
    if (q0 >= nd) return;
    const int ns = g_scnt[b], soff = g_soff[b], doff = g_doff[b];
    const int nQ = min(64, nd - q0);
    const int t = threadIdx.x, lane = t & 31, w = t >> 5;
    const int h = w & 3, qh = w >> 2;

    const uint32_t baseQ = (uint32_t)__cvta_generic_to_shared(qs);
    const uint32_t baseK = (uint32_t)__cvta_generic_to_shared(ks);
    const int nT = (ns + 31) >> 5;

    const int kr = t >> 3, kcc = (t & 7) * 4;
    #pragma unroll
    for (int i = 0; i < 4; i++) {
        int row = kr, c = kcc + i;
        int gr = soff + row; if (gr >= TOTAL) gr = TOTAL - 1;
        cpa16(baseK + ((row * 32 + (c ^ (row & 7))) * 8) * 2,
              g_kv + (size_t)gr * 256 + c * 8);
    }
    cpa_commit();

    #pragma unroll
    for (int i = 0; i < 4; i++) {
        int idx = t + i * 256;
        int row = idx >> 4, c = idx & 15;
        uint4 v = make_uint4(0, 0, 0, 0);
        if (row < nQ)
            v = *(const uint4*)(g_q + (size_t)(doff + q0 + row) * 128 + c * 8);
        *(uint4*)(qs + (row * 16 + (c ^ (row & 7))) * 8) = v;
    }

    float acc[2][4][4] = {};
    float den[2][2] = {};
    const float sc2 = 0.25504167f;   // log2(e)/sqrt(32)

    for (int tt = 0; tt < nT; tt++) {
        const int s0 = tt * 32;
        __syncthreads();
        if (tt + 1 < nT) {
            const uint32_t bufO = ((tt + 1) & 1) * (32 * 256 * 2);
            #pragma unroll
            for (int i = 0; i < 4; i++) {
                int row = kr, c = kcc + i;
                int gr = soff + (tt + 1) * 32 + row; if (gr >= TOTAL) gr = TOTAL - 1;
                cpa16(baseK + bufO + ((row * 32 + (c ^ (row & 7))) * 8) * 2,
                      g_kv + (size_t)gr * 256 + c * 8);
            }
        }
        cpa_commit();
        cpa_wait<1>();
        __syncthreads();

        const uint32_t bK = baseK + (tt & 1) * (32 * 256 * 2);

        float S[2][4][4] = {};
        #pragma unroll
        for (int kk = 0; kk < 2; kk++) {
            uint32_t af[2][4];
            #pragma unroll
            for (int f = 0; f < 2; f++) {
                int row = qh * 32 + f * 16 + (lane & 15);
                int c8 = (h * 4 + kk * 2 + (lane >> 4)) ^ (row & 7);
                ldsm4(af[f][0], af[f][1], af[f][2], af[f][3],
                      baseQ + (row * 16 + c8) * 16);
            }
            uint32_t bk2[2][4];
            #pragma unroll
            for (int p = 0; p < 2; p++) {
                int row = p * 16 + (lane & 7) + ((lane >> 4) << 3);
                int c8 = (h * 4 + kk * 2 + ((lane >> 3) & 1)) ^ (row & 7);
                ldsm4(bk2[p][0], bk2[p][1], bk2[p][2], bk2[p][3],
                      bK + (row * 32 + c8) * 16);
            }
            #pragma unroll
            for (int f = 0; f < 2; f++)
                #pragma unroll
                for (int n = 0; n < 4; n++)
                    mma_bf16(S[f][n], af[f], &bk2[n >> 1][(n & 1) * 2]);
        }

        uint32_t Ap[2][2][4];
        #pragma unroll
        for (int f = 0; f < 2; f++) {
            float d0 = 0.f, d1 = 0.f;
            #pragma unroll
            for (int n = 0; n < 4; n++) {
                int cb = s0 + n * 8 + (lane & 3) * 2;
                float e0 = ex2(S[f][n][0] * sc2); if (cb >= ns) e0 = 0.f;
                float e1 = ex2(S[f][n][1] * sc2); if (cb + 1 >= ns) e1 = 0.f;
                float e2 = ex2(S[f][n][2] * sc2); if (cb >= ns) e2 = 0.f;
                float e3 = ex2(S[f][n][3] * sc2); if (cb + 1 >= ns) e3 = 0.f;
                d0 += e0 + e1; d1 += e2 + e3;
                Ap[f][n >> 1][(n & 1) * 2]     = pk(e0, e1);
                Ap[f][n >> 1][(n & 1) * 2 + 1] = pk(e2, e3);
            }
            den[f][0] += d0; den[f][1] += d1;
        }

        #pragma unroll
        for (int kk = 0; kk < 2; kk++) {
            uint32_t bv[2][4];
            #pragma unroll
            for (int p = 0; p < 2; p++) {
                int row = kk * 16 + (lane & 15);
                int c8 = (16 + h * 4 + p * 2 + (lane >> 4)) ^ (row & 7);
                ldsm4t(bv[p][0], bv[p][1], bv[p][2], bv[p][3],
                       bK + (row * 32 + c8) * 16);
            }
            #pragma unroll
            for (int f = 0; f < 2; f++)
                #pragma unroll
                for (int n = 0; n < 4; n++)
                    mma_bf16(acc[f][n], Ap[f][kk], &bv[n >> 1][(n & 1) * 2]);
        }
    }

    #pragma unroll
    for (int f = 0; f < 2; f++)
        #pragma unroll
        for (int u = 0; u < 2; u++) {
            float v = den[f][u];
            v += __shfl_xor_sync(0xffffffffu, v, 1);
            v += __shfl_xor_sync(0xffffffffu, v, 2);
            den[f][u] = 1.f / v;
        }

    #pragma unroll
    for (int f = 0; f < 2; f++)
        #pragma unroll
        for (int n = 0; n < 4; n++)
            #pragma unroll
            for (int half = 0; half < 2; half++) {
                int rl = qh * 32 + f * 16 + (lane >> 2) + half * 8;
                if (rl < nQ) {
                    float inv = den[f][half];
                    __nv_bfloat162 o = __floats2bfloat162_rn(
                        acc[f][n][half * 2] * inv, acc[f][n][half * 2 + 1] * inv);
                    *(__nv_bfloat162*)(g_msg + (size_t)(doff + q0 + rl) * 128 +
                                       h * 32 + n * 8 + (lane & 3) * 2) = o;
                }
            }
}

// ------------------------------- launcher ----------------------------------
extern "C" void kernel_launch(void* const* d_in, const int* in_sizes, int n_in,
                              void* d_out, int out_size)
{
    const float* src_h = (const float*)d_in[0];
    const float* dst_h = (const float*)d_in[1];
    const void*  snv   = d_in[2];
    const void*  dnv   = d_in[3];
    const float* Wq = (const float*)d_in[4];  const float* bq = (const float*)d_in[5];
    const float* Wk = (const float*)d_in[6];  const float* bk = (const float*)d_in[7];
    const float* Wv = (const float*)d_in[8];  const float* bv = (const float*)d_in[9];
    const float* Wm = (const float*)d_in[10]; const float* bm = (const float*)d_in[11];
    const float* W1 = (const float*)d_in[12]; const float* b1 = (const float*)d_in[13];
    const float* g1 = (const float*)d_in[14]; const float* be1 = (const float*)d_in[15];
    const float* rm1 = (const float*)d_in[16]; const float* rv1 = (const float*)d_in[17];
    const float* W2 = (const float*)d_in[18]; const float* b2 = (const float*)d_in[19];
    const float* g2 = (const float*)d_in[20]; const float* be2 = (const float*)d_in[21];
    const float* rm2 = (const float*)d_in[22]; const float* rv2 = (const float*)d_in[23];
    float* out = (float*)d_out;

    __nv_bfloat16 *p_csrc, *p_cdst, *p_kv, *p_q, *p_msg, *p_x1;
    __nv_bfloat16 *p_Wkv, *p_Wqy, *p_W1bb, *p_WmT, *p_W1bp, *p_W2b;
    float *p_y1a, *p_bkvp, *p_bqy, *p_zero, *p_s1, *p_t1, *p_s2, *p_t2;
    cudaGetSymbolAddress((void**)&p_csrc, g_csrc);
    cudaGetSymbolAddress((void**)&p_cdst, g_cdst);
    cudaGetSymbolAddress((void**)&p_kv, g_kv);
    cudaGetSymbolAddress((void**)&p_q, g_q);
    cudaGetSymbolAddress((void**)&p_y1a, g_y1a);
    cudaGetSymbolAddress((void**)&p_msg, g_msg);
    cudaGetSymbolAddress((void**)&p_x1, g_x1);
    cudaGetSymbolAddress((void**)&p_Wkv, g_Wkv);
    cudaGetSymbolAddress((void**)&p_Wqy, g_Wqy);
    cudaGetSymbolAddress((void**)&p_W1bb, g_W1bb);
    cudaGetSymbolAddress((void**)&p_WmT, g_WmT);
    cudaGetSymbolAddress((void**)&p_W1bp, g_W1bp);
    cudaGetSymbolAddress((void**)&p_W2b, g_W2b);
    cudaGetSymbolAddress((void**)&p_bkvp, g_bkvp);
    cudaGetSymbolAddress((void**)&p_bqy, g_bqy);
    cudaGetSymbolAddress((void**)&p_zero, g_zero);
    cudaGetSymbolAddress((void**)&p_s1, g_s1);
    cudaGetSymbolAddress((void**)&p_t1, g_t1);
    cudaGetSymbolAddress((void**)&p_s2, g_s2);
    cudaGetSymbolAddress((void**)&p_t2, g_t2);

    // 1. fused front: setup | weight prep | activation convert
    k_front<<<3329, 256>>>(snv, dnv, src_h, dst_h, Wq, bq, Wk, bk, Wv, bv,
                           Wm, bm, W1, b1, g1, be1, rm1, rv1,
                           W2, b2, g2, be2, rm2, rv2);

    // 2. W1bp = W1b @ Wm  (tensor-core GEMM, M=256 N=128 K=128, zero bias)
    k_gemm<0, true><<<dim3(2, 2), 256>>>(p_W1bb, 128, p_WmT, p_zero,
                                         p_W1bp, 128, nullptr, 0, nullptr, nullptr);

    // 3. G1: kv = src @ [Wk;Wv]'.T    (bf16 out, head-major)
    k_gemm<0, true><<<dim3(192, 4), 256>>>(p_csrc, 256, p_Wkv, p_bkvp,
                                           p_kv, 256, nullptr, 0, nullptr, nullptr);
    // 4. G2 fused: q | y1a = dst @ [Wq;W1a].T  (MODE 3)
    k_gemm<3, true><<<dim3(192, 6), 256>>>(p_cdst, 256, p_Wqy, p_bqy,
                                           p_q, 128, nullptr, 0, nullptr, nullptr,
                                           p_y1a);
    // 5. attention
    k_attn<<<dim3(8, NSEG), 256>>>();
    // 6. G3: x1 = relu((msg @ W1bp'.T + y1a) * s1 + t1)  (bf16 out)
    k_gemm<1, true><<<dim3(192, 4), 256>>>(p_msg, 128, p_W1bp, nullptr,
                                           p_x1, 256, p_y1a, 256, p_s1, p_t1);
    // 7. G4: out = (x1 @ W2.T + b2) * s2 + t2 + dst_h    (fp32 out)
    k_gemm<2, false><<<dim3(192, 4), 256>>>(p_x1, 256, p_W2b, b2,
                                            out, 256, dst_h, 256, p_s2, p_t2);
}